// round 14
// baseline (speedup 1.0000x reference)
#include <cuda_runtime.h>
#include <cuda_bf16.h>
#include <cstdint>

// RNN autoencoder (GRU enc/dec) v10 = v8 (R12, 6484us) with symmetric
// epilogue (ONLY change). 128 blocks (64 clusters x 2); cluster owns MB=8
// batch rows, CTA `rank` owns hidden units [rank*128, rank*128+128).
// 256 threads: jl = tid&127, ks = tid>>7 (k-half). Each half donates
// partials for rows ro..ro+3 and finalizes rows rb..rb+3 (rb = ks*4),
// so all 8 warps work in the epilogue. Fused 6-stream layer-1 loop,
// unroll 8, two plain cluster_syncs per step.

#define TT   180
#define HH   256
#define BB   512
#define LATD 128
#define MB   8
#define NB2  128
#define NTH  256

typedef unsigned long long ull;
typedef unsigned int u32;

__device__ ulonglong2 g_Wp[6 * 3 * 64 * 256];
__device__ float g_z[BB * LATD];

__device__ __forceinline__ void fma2(ull& acc, ull a, ull b) {
    asm("fma.rn.f32x2 %0, %1, %2, %0;" : "+l"(acc) : "l"(a), "l"(b));
}
__device__ __forceinline__ void fma2v(ull& acc, ulonglong2 w, ulonglong2 h) {
    fma2(acc, w.x, h.x); fma2(acc, w.y, h.y);
}
__device__ __forceinline__ float psum(ull a) {
    float lo, hi;
    asm("mov.b64 {%0, %1}, %2;" : "=f"(lo), "=f"(hi) : "l"(a));
    return lo + hi;
}
__device__ __forceinline__ float sigm(float x) {
    return __fdividef(1.f, 1.f + __expf(-x));
}
__device__ __forceinline__ float tanhe(float x) {
    return 1.f - __fdividef(2.f, __expf(2.f * x) + 1.f);
}
__device__ __forceinline__ u32 smem_u32(const void* p) {
    u32 a;
    asm("{ .reg .u64 t; cvta.to.shared.u64 t, %1; cvt.u32.u64 %0, t; }"
        : "=r"(a) : "l"(p));
    return a;
}
__device__ __forceinline__ u32 mapa_rank(u32 a, u32 r) {
    u32 o;
    asm("mapa.shared::cluster.u32 %0, %1, %2;" : "=r"(o) : "r"(a), "r"(r));
    return o;
}
__device__ __forceinline__ void st_cluster(u32 a, float v) {
    asm volatile("st.shared::cluster.f32 [%0], %1;" :: "r"(a), "f"(v) : "memory");
}
__device__ __forceinline__ void cluster_sync() {
    asm volatile("barrier.cluster.arrive.aligned;" ::: "memory");
    asm volatile("barrier.cluster.wait.aligned;" ::: "memory");
}
__device__ __forceinline__ u32 ctarank() {
    u32 r; asm("mov.u32 %0, %%cluster_ctarank;" : "=r"(r)); return r;
}

// ---------------------------------------------------------------------------
__global__ void pack_kernel(const float* __restrict__ W0, const float* __restrict__ W1,
                            const float* __restrict__ W2, const float* __restrict__ W3,
                            const float* __restrict__ W4, const float* __restrict__ W5)
{
    int m  = blockIdx.x / 192;
    int r  = blockIdx.x % 192;
    int g  = r >> 6;
    int k4 = r & 63;
    int j  = threadIdx.x;
    const float* W = W0;
    if (m == 1) W = W1; else if (m == 2) W = W2;
    else if (m == 3) W = W3; else if (m == 4) W = W4; else if (m == 5) W = W5;
    const float* row = W + (size_t)(g * 256 + j) * 256 + k4 * 4;
    float4 v = make_float4(row[0], row[1], row[2], row[3]);
    g_Wp[(size_t)((m * 3 + g) * 64 + k4) * 256 + j] = *(ulonglong2*)&v;
}

// Shared layout (floats): h0[2][8][256] @0, h1[2][8][256] @4096,
// red[32][128] @8192, (enc) x[8][180][2] @12288
#define OFF_H0  0
#define OFF_H1  4096
#define OFF_RED 8192
#define OFF_X   12288
#define ENC_SMEM_FLOATS (12288 + MB * TT * 2)
#define DEC_SMEM_FLOATS 12288

// ---------------------------------------------------------------------------
// Encoder
// ---------------------------------------------------------------------------
__global__ __launch_bounds__(NTH, 1) __cluster_dims__(2, 1, 1)
void enc_kernel(const float* __restrict__ x,
                const float* __restrict__ ln_w, const float* __restrict__ ln_b,
                const float* __restrict__ Wih0,
                const float* __restrict__ bih0, const float* __restrict__ bhh0,
                const float* __restrict__ bih1, const float* __restrict__ bhh1,
                const float* __restrict__ fce_w, const float* __restrict__ fce_b,
                float* __restrict__ z_out, int write_zout)
{
    extern __shared__ __align__(16) float sm[];
    float* h0b = sm + OFF_H0;
    float* h1b = sm + OFF_H1;
    float* red = sm + OFF_RED;
    float* xb  = sm + OFF_X;

    const int tid  = threadIdx.x;
    const int jl   = tid & 127;
    const int ks   = tid >> 7;
    const u32 rank = ctarank();
    const int j    = (int)rank * 128 + jl;
    const int base = (blockIdx.x >> 1) * MB;
    const int w    = tid >> 5;
    const int lane = tid & 31;
    const int rb   = ks * 4;          // rows this thread finalizes
    const int ro   = (ks ^ 1) * 4;    // rows this thread donates

    for (int i = tid; i < 4096; i += NTH) { h0b[i] = 0.f; h1b[i] = 0.f; }

    // LayerNorm per batch row (warps 0..7 -> rows 0..7)
    {
        const int b = w;
        const float* xr = x + (size_t)(base + b) * TT * 2;
        float s = 0.f, s2 = 0.f;
        for (int i = lane; i < TT * 2; i += 32) {
            float v = xr[i]; s += v; s2 += v * v;
        }
        #pragma unroll
        for (int o = 16; o > 0; o >>= 1) {
            s  += __shfl_xor_sync(0xffffffffu, s, o);
            s2 += __shfl_xor_sync(0xffffffffu, s2, o);
        }
        const float inv = 1.f / (TT * 2);
        float mu  = s * inv;
        float var = s2 * inv - mu * mu;
        float rs  = rsqrtf(var + 1e-5f);
        for (int i = lane; i < TT * 2; i += 32)
            xb[b * TT * 2 + i] = (xr[i] - mu) * rs * ln_w[i] + ln_b[i];
    }
    __syncthreads();

    const float e0wr0 = Wih0[j * 2 + 0],            e0wr1 = Wih0[j * 2 + 1];
    const float e0wz0 = Wih0[(HH + j) * 2 + 0],     e0wz1 = Wih0[(HH + j) * 2 + 1];
    const float e0wn0 = Wih0[(2 * HH + j) * 2 + 0], e0wn1 = Wih0[(2 * HH + j) * 2 + 1];
    const float c0r  = bih0[j] + bhh0[j];
    const float c0z  = bih0[HH + j] + bhh0[HH + j];
    const float c0in = bih0[2 * HH + j];
    const float c0hn = bhh0[2 * HH + j];
    const float c1r  = bih1[j] + bhh1[j];
    const float c1z  = bih1[HH + j] + bhh1[HH + j];
    const float c1in = bih1[2 * HH + j];
    const float c1hn = bhh1[2 * HH + j];

    const ulonglong2* P0r = g_Wp + (size_t)0 * 16384 + j;
    const ulonglong2* P0z = g_Wp + (size_t)1 * 16384 + j;
    const ulonglong2* P0n = g_Wp + (size_t)2 * 16384 + j;
    const ulonglong2* P1r = g_Wp + (size_t)3 * 16384 + j;
    const ulonglong2* P1z = g_Wp + (size_t)4 * 16384 + j;
    const ulonglong2* P1n = g_Wp + (size_t)5 * 16384 + j;
    const ulonglong2* P2r = g_Wp + (size_t)6 * 16384 + j;
    const ulonglong2* P2z = g_Wp + (size_t)7 * 16384 + j;
    const ulonglong2* P2n = g_Wp + (size_t)8 * 16384 + j;

    const u32 loc_base = smem_u32(sm);
    const u32 rem_base = mapa_rank(loc_base, rank ^ 1);
    const int k0 = ks * 32;
    cluster_sync();

    int s = 0;
    for (int t = 0; t < TT; t++) {
        const float* h0c = h0b + s * 2048;
        float*       h0n = h0b + (s ^ 1) * 2048;
        const float* h1c = h1b + s * 2048;
        float*       h1n = h1b + (s ^ 1) * 2048;

        // ---- layer 0 matvec over this thread's k-half ----
        ull ar[MB], az[MB], an_[MB];
        #pragma unroll
        for (int b = 0; b < MB; b++) { ar[b] = 0ull; az[b] = 0ull; an_[b] = 0ull; }
        #pragma unroll 8
        for (int k4 = k0; k4 < k0 + 32; k4++) {
            ulonglong2 wr = P0r[k4 * 256];
            ulonglong2 wz = P0z[k4 * 256];
            ulonglong2 wn = P0n[k4 * 256];
            #pragma unroll
            for (int b = 0; b < MB; b++) {
                ulonglong2 h = *(const ulonglong2*)&h0c[b * 256 + k4 * 4];
                fma2v(ar[b], wr, h); fma2v(az[b], wz, h); fma2v(an_[b], wn, h);
            }
        }
        // symmetric: donate rows ro..ro+3, finalize rows rb..rb+3
        #pragma unroll
        for (int i = 0; i < 4; i++) {
            int b = ro + i;
            red[(0 * 8 + b) * 128 + jl] = psum(ar[b]);
            red[(1 * 8 + b) * 128 + jl] = psum(az[b]);
            red[(2 * 8 + b) * 128 + jl] = psum(an_[b]);
        }
        __syncthreads();
        #pragma unroll
        for (int i = 0; i < 4; i++) {
            int b = rb + i;
            float sr = psum(ar[b])  + red[(0 * 8 + b) * 128 + jl];
            float sz = psum(az[b])  + red[(1 * 8 + b) * 128 + jl];
            float sn = psum(an_[b]) + red[(2 * 8 + b) * 128 + jl];
            float x0 = xb[b * TT * 2 + t * 2 + 0];
            float x1 = xb[b * TT * 2 + t * 2 + 1];
            float rg = sigm(sr + c0r + e0wr0 * x0 + e0wr1 * x1);
            float zg = sigm(sz + c0z + e0wz0 * x0 + e0wz1 * x1);
            float n  = tanhe(c0in + e0wn0 * x0 + e0wn1 * x1 + rg * (sn + c0hn));
            float hn = (1.f - zg) * n + zg * h0c[b * 256 + j];
            h0n[b * 256 + j] = hn;
            st_cluster(rem_base + (u32)(OFF_H0 + (s ^ 1) * 2048 + b * 256 + j) * 4u, hn);
        }
        cluster_sync();

        // ---- layer 1 fused: gi = Wih1 @ h0n, gh = Whh1 @ h1c ----
        ull br_[MB], bz_[MB], bin_[MB], bhn_[MB];
        #pragma unroll
        for (int b = 0; b < MB; b++) { br_[b] = 0ull; bz_[b] = 0ull; bin_[b] = 0ull; bhn_[b] = 0ull; }
        #pragma unroll 8
        for (int k4 = k0; k4 < k0 + 32; k4++) {
            ulonglong2 ur = P1r[k4 * 256];
            ulonglong2 uz = P1z[k4 * 256];
            ulonglong2 un = P1n[k4 * 256];
            ulonglong2 vr = P2r[k4 * 256];
            ulonglong2 vz = P2z[k4 * 256];
            ulonglong2 vn = P2n[k4 * 256];
            #pragma unroll
            for (int b = 0; b < MB; b++) {
                ulonglong2 u = *(const ulonglong2*)&h0n[b * 256 + k4 * 4];
                fma2v(br_[b], ur, u); fma2v(bz_[b], uz, u); fma2v(bin_[b], un, u);
                ulonglong2 h = *(const ulonglong2*)&h1c[b * 256 + k4 * 4];
                fma2v(br_[b], vr, h); fma2v(bz_[b], vz, h); fma2v(bhn_[b], vn, h);
            }
        }
        #pragma unroll
        for (int i = 0; i < 4; i++) {
            int b = ro + i;
            red[(0 * 8 + b) * 128 + jl] = psum(br_[b]);
            red[(1 * 8 + b) * 128 + jl] = psum(bz_[b]);
            red[(2 * 8 + b) * 128 + jl] = psum(bin_[b]);
            red[(3 * 8 + b) * 128 + jl] = psum(bhn_[b]);
        }
        __syncthreads();
        #pragma unroll
        for (int i = 0; i < 4; i++) {
            int b = rb + i;
            float sr = psum(br_[b])  + red[(0 * 8 + b) * 128 + jl];
            float sz = psum(bz_[b])  + red[(1 * 8 + b) * 128 + jl];
            float si = psum(bin_[b]) + red[(2 * 8 + b) * 128 + jl];
            float sh = psum(bhn_[b]) + red[(3 * 8 + b) * 128 + jl];
            float rg = sigm(sr + c1r);
            float zg = sigm(sz + c1z);
            float n  = tanhe(si + c1in + rg * (sh + c1hn));
            float hn = (1.f - zg) * n + zg * h1c[b * 256 + j];
            h1n[b * 256 + j] = hn;
            st_cluster(rem_base + (u32)(OFF_H1 + (s ^ 1) * 2048 + b * 256 + j) * 4u, hn);
        }
        cluster_sync();
        s ^= 1;
    }

    // z = tanh(h1_final @ fce_w.T + fce_b); each CTA does 4 of its 8 rows
    {
        const float* h1f = h1b + s * 2048;
        const int l  = tid & (LATD - 1);
        const int b0 = (int)rank * 4 + (tid >> 7) * 2;
        const float* wl = fce_w + (size_t)l * HH;
        for (int b = b0; b < b0 + 2; b++) {
            float acc = 0.f;
            #pragma unroll 8
            for (int k = 0; k < HH; k++) acc += wl[k] * h1f[b * 256 + k];
            float zz = tanhf(acc + fce_b[l]);
            g_z[(size_t)(base + b) * LATD + l] = zz;
            if (write_zout) z_out[(size_t)(base + b) * LATD + l] = zz;
        }
    }
    cluster_sync();
}

// ---------------------------------------------------------------------------
// Decoder
// ---------------------------------------------------------------------------
__global__ __launch_bounds__(NTH, 1) __cluster_dims__(2, 1, 1)
void dec_kernel(const float* __restrict__ Wih0,
                const float* __restrict__ bih0, const float* __restrict__ bhh0,
                const float* __restrict__ bih1, const float* __restrict__ bhh1,
                const float* __restrict__ fcd_w, const float* __restrict__ fcd_b,
                const float* __restrict__ fco_w, const float* __restrict__ fco_b,
                float* __restrict__ out)
{
    extern __shared__ __align__(16) float sm[];
    float* h0b = sm + OFF_H0;
    float* h1b = sm + OFF_H1;
    float* red = sm + OFF_RED;
    __shared__ float yb[MB][2];

    const int tid  = threadIdx.x;
    const int jl   = tid & 127;
    const int ks   = tid >> 7;
    const u32 rank = ctarank();
    const int j    = (int)rank * 128 + jl;
    const int base = (blockIdx.x >> 1) * MB;
    const int w    = tid >> 5;
    const int lane = tid & 31;
    const int rb   = ks * 4;
    const int ro   = (ks ^ 1) * 4;

    // Init full h replica from fc_dec(z), raw row-major reshape:
    // dec_h[l][gb][u] = fcd_b[c'] + z[l*256+gb/2].fcd_w[c'], c' = (gb&1)*256+u
    {
        const int u = tid;
        #pragma unroll
        for (int b = 0; b < MB; b++) {
            int gb = base + b;
            int cr = ((gb & 1) << 8) + u;
            const float* wrow = fcd_w + (size_t)cr * LATD;
            const float* z0 = g_z + (size_t)(gb >> 1) * LATD;
            const float* z1 = g_z + (size_t)(256 + (gb >> 1)) * LATD;
            float a0 = fcd_b[cr], a1 = a0;
            #pragma unroll 8
            for (int k = 0; k < LATD; k++) {
                float wv = wrow[k];
                a0 += wv * z0[k];
                a1 += wv * z1[k];
            }
            h0b[b * 256 + u] = a0;
            h1b[b * 256 + u] = a1;
        }
    }
    if (tid < MB * 2) yb[tid >> 1][tid & 1] = 0.f;
    __syncthreads();

    const float d0wr0 = Wih0[j * 2 + 0],            d0wr1 = Wih0[j * 2 + 1];
    const float d0wz0 = Wih0[(HH + j) * 2 + 0],     d0wz1 = Wih0[(HH + j) * 2 + 1];
    const float d0wn0 = Wih0[(2 * HH + j) * 2 + 0], d0wn1 = Wih0[(2 * HH + j) * 2 + 1];
    const float c0r  = bih0[j] + bhh0[j];
    const float c0z  = bih0[HH + j] + bhh0[HH + j];
    const float c0in = bih0[2 * HH + j];
    const float c0hn = bhh0[2 * HH + j];
    const float c1r  = bih1[j] + bhh1[j];
    const float c1z  = bih1[HH + j] + bhh1[HH + j];
    const float c1in = bih1[2 * HH + j];
    const float c1hn = bhh1[2 * HH + j];

    const ulonglong2* P0r = g_Wp + (size_t) 9 * 16384 + j;
    const ulonglong2* P0z = g_Wp + (size_t)10 * 16384 + j;
    const ulonglong2* P0n = g_Wp + (size_t)11 * 16384 + j;
    const ulonglong2* P1r = g_Wp + (size_t)12 * 16384 + j;
    const ulonglong2* P1z = g_Wp + (size_t)13 * 16384 + j;
    const ulonglong2* P1n = g_Wp + (size_t)14 * 16384 + j;
    const ulonglong2* P2r = g_Wp + (size_t)15 * 16384 + j;
    const ulonglong2* P2z = g_Wp + (size_t)16 * 16384 + j;
    const ulonglong2* P2n = g_Wp + (size_t)17 * 16384 + j;

    const u32 loc_base = smem_u32(sm);
    const u32 rem_base = mapa_rank(loc_base, rank ^ 1);
    const int k0 = ks * 32;
    cluster_sync();

    int s = 0;
    for (int t = 0; t < TT; t++) {
        const float* h0c = h0b + s * 2048;
        float*       h0n = h0b + (s ^ 1) * 2048;
        const float* h1c = h1b + s * 2048;
        float*       h1n = h1b + (s ^ 1) * 2048;

        // ---- layer 0 matvec ----
        ull ar[MB], az[MB], an_[MB];
        #pragma unroll
        for (int b = 0; b < MB; b++) { ar[b] = 0ull; az[b] = 0ull; an_[b] = 0ull; }
        #pragma unroll 8
        for (int k4 = k0; k4 < k0 + 32; k4++) {
            ulonglong2 wr = P0r[k4 * 256];
            ulonglong2 wz = P0z[k4 * 256];
            ulonglong2 wn = P0n[k4 * 256];
            #pragma unroll
            for (int b = 0; b < MB; b++) {
                ulonglong2 h = *(const ulonglong2*)&h0c[b * 256 + k4 * 4];
                fma2v(ar[b], wr, h); fma2v(az[b], wz, h); fma2v(an_[b], wn, h);
            }
        }
        #pragma unroll
        for (int i = 0; i < 4; i++) {
            int b = ro + i;
            red[(0 * 8 + b) * 128 + jl] = psum(ar[b]);
            red[(1 * 8 + b) * 128 + jl] = psum(az[b]);
            red[(2 * 8 + b) * 128 + jl] = psum(an_[b]);
        }
        __syncthreads();
        #pragma unroll
        for (int i = 0; i < 4; i++) {
            int b = rb + i;
            float sr = psum(ar[b])  + red[(0 * 8 + b) * 128 + jl];
            float sz = psum(az[b])  + red[(1 * 8 + b) * 128 + jl];
            float sn = psum(an_[b]) + red[(2 * 8 + b) * 128 + jl];
            float x0 = yb[b][0], x1 = yb[b][1];
            float rg = sigm(sr + c0r + d0wr0 * x0 + d0wr1 * x1);
            float zg = sigm(sz + c0z + d0wz0 * x0 + d0wz1 * x1);
            float n  = tanhe(c0in + d0wn0 * x0 + d0wn1 * x1 + rg * (sn + c0hn));
            float hn = (1.f - zg) * n + zg * h0c[b * 256 + j];
            h0n[b * 256 + j] = hn;
            st_cluster(rem_base + (u32)(OFF_H0 + (s ^ 1) * 2048 + b * 256 + j) * 4u, hn);
        }
        cluster_sync();

        // ---- layer 1 fused ----
        ull br_[MB], bz_[MB], bin_[MB], bhn_[MB];
        #pragma unroll
        for (int b = 0; b < MB; b++) { br_[b] = 0ull; bz_[b] = 0ull; bin_[b] = 0ull; bhn_[b] = 0ull; }
        #pragma unroll 8
        for (int k4 = k0; k4 < k0 + 32; k4++) {
            ulonglong2 ur = P1r[k4 * 256];
            ulonglong2 uz = P1z[k4 * 256];
            ulonglong2 un = P1n[k4 * 256];
            ulonglong2 vr = P2r[k4 * 256];
            ulonglong2 vz = P2z[k4 * 256];
            ulonglong2 vn = P2n[k4 * 256];
            #pragma unroll
            for (int b = 0; b < MB; b++) {
                ulonglong2 u = *(const ulonglong2*)&h0n[b * 256 + k4 * 4];
                fma2v(br_[b], ur, u); fma2v(bz_[b], uz, u); fma2v(bin_[b], un, u);
                ulonglong2 h = *(const ulonglong2*)&h1c[b * 256 + k4 * 4];
                fma2v(br_[b], vr, h); fma2v(bz_[b], vz, h); fma2v(bhn_[b], vn, h);
            }
        }
        #pragma unroll
        for (int i = 0; i < 4; i++) {
            int b = ro + i;
            red[(0 * 8 + b) * 128 + jl] = psum(br_[b]);
            red[(1 * 8 + b) * 128 + jl] = psum(bz_[b]);
            red[(2 * 8 + b) * 128 + jl] = psum(bin_[b]);
            red[(3 * 8 + b) * 128 + jl] = psum(bhn_[b]);
        }
        __syncthreads();
        #pragma unroll
        for (int i = 0; i < 4; i++) {
            int b = rb + i;
            float sr = psum(br_[b])  + red[(0 * 8 + b) * 128 + jl];
            float sz = psum(bz_[b])  + red[(1 * 8 + b) * 128 + jl];
            float si = psum(bin_[b]) + red[(2 * 8 + b) * 128 + jl];
            float sh = psum(bhn_[b]) + red[(3 * 8 + b) * 128 + jl];
            float rg = sigm(sr + c1r);
            float zg = sigm(sz + c1z);
            float n  = tanhe(si + c1in + rg * (sh + c1hn));
            float hn = (1.f - zg) * n + zg * h1c[b * 256 + j];
            h1n[b * 256 + j] = hn;
            st_cluster(rem_base + (u32)(OFF_H1 + (s ^ 1) * 2048 + b * 256 + j) * 4u, hn);
        }
        cluster_sync();

        // ---- output head: warps 0..7 -> rows 0..7 (full h1n valid now) ----
        {
            const int b = w;
            float a0 = 0.f, a1 = 0.f;
            const float* w0 = fco_w;
            const float* w1 = fco_w + HH;
            #pragma unroll
            for (int k = lane; k < HH; k += 32) {
                float hv = h1n[b * 256 + k];
                a0 += w0[k] * hv;
                a1 += w1[k] * hv;
            }
            #pragma unroll
            for (int o = 16; o > 0; o >>= 1) {
                a0 += __shfl_xor_sync(0xffffffffu, a0, o);
                a1 += __shfl_xor_sync(0xffffffffu, a1, o);
            }
            if (lane == 0) {
                float y0 = a0 + fco_b[0];
                float y1 = a1 + fco_b[1];
                yb[b][0] = y0;
                yb[b][1] = y1;
                if (rank == 0) {
                    int gb = base + b;
                    out[((size_t)gb * TT + t) * 2 + 0] = y0;
                    out[((size_t)gb * TT + t) * 2 + 1] = y1;
                }
            }
        }
        __syncthreads();
        s ^= 1;
    }
    cluster_sync();
}

// ---------------------------------------------------------------------------
extern "C" void kernel_launch(void* const* d_in, const int* in_sizes, int n_in,
                              void* d_out, int out_size) {
    const float* x        = (const float*)d_in[0];
    const float* ln_w     = (const float*)d_in[1];
    const float* ln_b     = (const float*)d_in[2];
    const float* enc_Wih0 = (const float*)d_in[3];
    const float* enc_Whh0 = (const float*)d_in[4];
    const float* enc_bih0 = (const float*)d_in[5];
    const float* enc_bhh0 = (const float*)d_in[6];
    const float* enc_Wih1 = (const float*)d_in[7];
    const float* enc_Whh1 = (const float*)d_in[8];
    const float* enc_bih1 = (const float*)d_in[9];
    const float* enc_bhh1 = (const float*)d_in[10];
    const float* dec_Wih0 = (const float*)d_in[11];
    const float* dec_Whh0 = (const float*)d_in[12];
    const float* dec_bih0 = (const float*)d_in[13];
    const float* dec_bhh0 = (const float*)d_in[14];
    const float* dec_Wih1 = (const float*)d_in[15];
    const float* dec_Whh1 = (const float*)d_in[16];
    const float* dec_bih1 = (const float*)d_in[17];
    const float* dec_bhh1 = (const float*)d_in[18];
    const float* fc_enc_w = (const float*)d_in[19];
    const float* fc_enc_b = (const float*)d_in[20];
    const float* fc_dec_w = (const float*)d_in[21];
    const float* fc_dec_b = (const float*)d_in[22];
    const float* fc_out_w = (const float*)d_in[23];
    const float* fc_out_b = (const float*)d_in[24];

    float* out = (float*)d_out;
    const int recon_elems = BB * TT * 2;             // 184320
    const int z_elems     = BB * LATD;               // 65536
    int write_z = (out_size >= recon_elems + z_elems) ? 1 : 0;
    float* z_out = out + recon_elems;

    static int attr_done = 0;
    if (!attr_done) {
        cudaFuncSetAttribute(enc_kernel, cudaFuncAttributeMaxDynamicSharedMemorySize,
                             ENC_SMEM_FLOATS * 4);
        cudaFuncSetAttribute(dec_kernel, cudaFuncAttributeMaxDynamicSharedMemorySize,
                             DEC_SMEM_FLOATS * 4);
        attr_done = 1;
    }

    pack_kernel<<<6 * 192, 256>>>(enc_Whh0, enc_Wih1, enc_Whh1,
                                  dec_Whh0, dec_Wih1, dec_Whh1);

    enc_kernel<<<NB2, NTH, ENC_SMEM_FLOATS * 4>>>(
        x, ln_w, ln_b, enc_Wih0, enc_bih0, enc_bhh0,
        enc_bih1, enc_bhh1, fc_enc_w, fc_enc_b, z_out, write_z);

    dec_kernel<<<NB2, NTH, DEC_SMEM_FLOATS * 4>>>(
        dec_Wih0, dec_bih0, dec_bhh0, dec_bih1, dec_bhh1,
        fc_dec_w, fc_dec_b, fc_out_w, fc_out_b, out);
}

// round 15
// speedup vs baseline: 1.3072x; 1.3072x over previous
#include <cuda_runtime.h>
#include <cuda_bf16.h>
#include <cstdint>

// RNN autoencoder (GRU enc/dec) v11 = v8 (R12, 6484us) with layer-0 k-loop
// unroll 16 (ONLY change; layer-1 stays 8 due to register budget).
// 128 blocks (64 clusters x 2); cluster owns MB=8 batch rows, CTA `rank`
// owns hidden units [rank*128, rank*128+128). 256 threads: jl = tid&127,
// ks = tid>>7 (k-half). Partials via SMEM red (ks=1 donates, ks=0
// finalizes); fused 6-stream layer-1 loop; two plain cluster_syncs per step.

#define TT   180
#define HH   256
#define BB   512
#define LATD 128
#define MB   8
#define NB2  128
#define NTH  256

typedef unsigned long long ull;
typedef unsigned int u32;

__device__ ulonglong2 g_Wp[6 * 3 * 64 * 256];
__device__ float g_z[BB * LATD];

__device__ __forceinline__ void fma2(ull& acc, ull a, ull b) {
    asm("fma.rn.f32x2 %0, %1, %2, %0;" : "+l"(acc) : "l"(a), "l"(b));
}
__device__ __forceinline__ void fma2v(ull& acc, ulonglong2 w, ulonglong2 h) {
    fma2(acc, w.x, h.x); fma2(acc, w.y, h.y);
}
__device__ __forceinline__ float psum(ull a) {
    float lo, hi;
    asm("mov.b64 {%0, %1}, %2;" : "=f"(lo), "=f"(hi) : "l"(a));
    return lo + hi;
}
__device__ __forceinline__ float sigm(float x) {
    return __fdividef(1.f, 1.f + __expf(-x));
}
__device__ __forceinline__ float tanhe(float x) {
    return 1.f - __fdividef(2.f, __expf(2.f * x) + 1.f);
}
__device__ __forceinline__ u32 smem_u32(const void* p) {
    u32 a;
    asm("{ .reg .u64 t; cvta.to.shared.u64 t, %1; cvt.u32.u64 %0, t; }"
        : "=r"(a) : "l"(p));
    return a;
}
__device__ __forceinline__ u32 mapa_rank(u32 a, u32 r) {
    u32 o;
    asm("mapa.shared::cluster.u32 %0, %1, %2;" : "=r"(o) : "r"(a), "r"(r));
    return o;
}
__device__ __forceinline__ void st_cluster(u32 a, float v) {
    asm volatile("st.shared::cluster.f32 [%0], %1;" :: "r"(a), "f"(v) : "memory");
}
__device__ __forceinline__ void cluster_sync() {
    asm volatile("barrier.cluster.arrive.aligned;" ::: "memory");
    asm volatile("barrier.cluster.wait.aligned;" ::: "memory");
}
__device__ __forceinline__ u32 ctarank() {
    u32 r; asm("mov.u32 %0, %%cluster_ctarank;" : "=r"(r)); return r;
}

// ---------------------------------------------------------------------------
__global__ void pack_kernel(const float* __restrict__ W0, const float* __restrict__ W1,
                            const float* __restrict__ W2, const float* __restrict__ W3,
                            const float* __restrict__ W4, const float* __restrict__ W5)
{
    int m  = blockIdx.x / 192;
    int r  = blockIdx.x % 192;
    int g  = r >> 6;
    int k4 = r & 63;
    int j  = threadIdx.x;
    const float* W = W0;
    if (m == 1) W = W1; else if (m == 2) W = W2;
    else if (m == 3) W = W3; else if (m == 4) W = W4; else if (m == 5) W = W5;
    const float* row = W + (size_t)(g * 256 + j) * 256 + k4 * 4;
    float4 v = make_float4(row[0], row[1], row[2], row[3]);
    g_Wp[(size_t)((m * 3 + g) * 64 + k4) * 256 + j] = *(ulonglong2*)&v;
}

// Shared layout (floats): h0[2][8][256] @0, h1[2][8][256] @4096,
// red[32][128] @8192, (enc) x[8][180][2] @12288
#define OFF_H0  0
#define OFF_H1  4096
#define OFF_RED 8192
#define OFF_X   12288
#define ENC_SMEM_FLOATS (12288 + MB * TT * 2)
#define DEC_SMEM_FLOATS 12288

// ---------------------------------------------------------------------------
// Encoder
// ---------------------------------------------------------------------------
__global__ __launch_bounds__(NTH, 1) __cluster_dims__(2, 1, 1)
void enc_kernel(const float* __restrict__ x,
                const float* __restrict__ ln_w, const float* __restrict__ ln_b,
                const float* __restrict__ Wih0,
                const float* __restrict__ bih0, const float* __restrict__ bhh0,
                const float* __restrict__ bih1, const float* __restrict__ bhh1,
                const float* __restrict__ fce_w, const float* __restrict__ fce_b,
                float* __restrict__ z_out, int write_zout)
{
    extern __shared__ __align__(16) float sm[];
    float* h0b = sm + OFF_H0;
    float* h1b = sm + OFF_H1;
    float* red = sm + OFF_RED;
    float* xb  = sm + OFF_X;

    const int tid  = threadIdx.x;
    const int jl   = tid & 127;
    const int ks   = tid >> 7;
    const u32 rank = ctarank();
    const int j    = (int)rank * 128 + jl;
    const int base = (blockIdx.x >> 1) * MB;
    const int w    = tid >> 5;
    const int lane = tid & 31;

    for (int i = tid; i < 4096; i += NTH) { h0b[i] = 0.f; h1b[i] = 0.f; }

    // LayerNorm per batch row (warps 0..7 -> rows 0..7)
    {
        const int b = w;
        const float* xr = x + (size_t)(base + b) * TT * 2;
        float s = 0.f, s2 = 0.f;
        for (int i = lane; i < TT * 2; i += 32) {
            float v = xr[i]; s += v; s2 += v * v;
        }
        #pragma unroll
        for (int o = 16; o > 0; o >>= 1) {
            s  += __shfl_xor_sync(0xffffffffu, s, o);
            s2 += __shfl_xor_sync(0xffffffffu, s2, o);
        }
        const float inv = 1.f / (TT * 2);
        float mu  = s * inv;
        float var = s2 * inv - mu * mu;
        float rs  = rsqrtf(var + 1e-5f);
        for (int i = lane; i < TT * 2; i += 32)
            xb[b * TT * 2 + i] = (xr[i] - mu) * rs * ln_w[i] + ln_b[i];
    }
    __syncthreads();

    const float e0wr0 = Wih0[j * 2 + 0],            e0wr1 = Wih0[j * 2 + 1];
    const float e0wz0 = Wih0[(HH + j) * 2 + 0],     e0wz1 = Wih0[(HH + j) * 2 + 1];
    const float e0wn0 = Wih0[(2 * HH + j) * 2 + 0], e0wn1 = Wih0[(2 * HH + j) * 2 + 1];
    const float c0r  = bih0[j] + bhh0[j];
    const float c0z  = bih0[HH + j] + bhh0[HH + j];
    const float c0in = bih0[2 * HH + j];
    const float c0hn = bhh0[2 * HH + j];
    const float c1r  = bih1[j] + bhh1[j];
    const float c1z  = bih1[HH + j] + bhh1[HH + j];
    const float c1in = bih1[2 * HH + j];
    const float c1hn = bhh1[2 * HH + j];

    const ulonglong2* P0r = g_Wp + (size_t)0 * 16384 + j;
    const ulonglong2* P0z = g_Wp + (size_t)1 * 16384 + j;
    const ulonglong2* P0n = g_Wp + (size_t)2 * 16384 + j;
    const ulonglong2* P1r = g_Wp + (size_t)3 * 16384 + j;
    const ulonglong2* P1z = g_Wp + (size_t)4 * 16384 + j;
    const ulonglong2* P1n = g_Wp + (size_t)5 * 16384 + j;
    const ulonglong2* P2r = g_Wp + (size_t)6 * 16384 + j;
    const ulonglong2* P2z = g_Wp + (size_t)7 * 16384 + j;
    const ulonglong2* P2n = g_Wp + (size_t)8 * 16384 + j;

    const u32 loc_base = smem_u32(sm);
    const u32 rem_base = mapa_rank(loc_base, rank ^ 1);
    const int k0 = ks * 32;
    cluster_sync();

    int s = 0;
    for (int t = 0; t < TT; t++) {
        const float* h0c = h0b + s * 2048;
        float*       h0n = h0b + (s ^ 1) * 2048;
        const float* h1c = h1b + s * 2048;
        float*       h1n = h1b + (s ^ 1) * 2048;

        // ---- layer 0 matvec over this thread's k-half (unroll 16) ----
        ull ar[MB], az[MB], an_[MB];
        #pragma unroll
        for (int b = 0; b < MB; b++) { ar[b] = 0ull; az[b] = 0ull; an_[b] = 0ull; }
        #pragma unroll 16
        for (int k4 = k0; k4 < k0 + 32; k4++) {
            ulonglong2 wr = P0r[k4 * 256];
            ulonglong2 wz = P0z[k4 * 256];
            ulonglong2 wn = P0n[k4 * 256];
            #pragma unroll
            for (int b = 0; b < MB; b++) {
                ulonglong2 h = *(const ulonglong2*)&h0c[b * 256 + k4 * 4];
                fma2v(ar[b], wr, h); fma2v(az[b], wz, h); fma2v(an_[b], wn, h);
            }
        }
        if (ks) {
            #pragma unroll
            for (int b = 0; b < MB; b++) {
                red[(0 * 8 + b) * 128 + jl] = psum(ar[b]);
                red[(1 * 8 + b) * 128 + jl] = psum(az[b]);
                red[(2 * 8 + b) * 128 + jl] = psum(an_[b]);
            }
        }
        __syncthreads();
        if (!ks) {
            #pragma unroll
            for (int b = 0; b < MB; b++) {
                float sr = psum(ar[b])  + red[(0 * 8 + b) * 128 + jl];
                float sz = psum(az[b])  + red[(1 * 8 + b) * 128 + jl];
                float sn = psum(an_[b]) + red[(2 * 8 + b) * 128 + jl];
                float x0 = xb[b * TT * 2 + t * 2 + 0];
                float x1 = xb[b * TT * 2 + t * 2 + 1];
                float rg = sigm(sr + c0r + e0wr0 * x0 + e0wr1 * x1);
                float zg = sigm(sz + c0z + e0wz0 * x0 + e0wz1 * x1);
                float n  = tanhe(c0in + e0wn0 * x0 + e0wn1 * x1 + rg * (sn + c0hn));
                float hn = (1.f - zg) * n + zg * h0c[b * 256 + j];
                h0n[b * 256 + j] = hn;
                st_cluster(rem_base + (u32)(OFF_H0 + (s ^ 1) * 2048 + b * 256 + j) * 4u, hn);
            }
        }
        cluster_sync();

        // ---- layer 1 fused: gi = Wih1 @ h0n, gh = Whh1 @ h1c (unroll 8) ----
        ull br_[MB], bz_[MB], bin_[MB], bhn_[MB];
        #pragma unroll
        for (int b = 0; b < MB; b++) { br_[b] = 0ull; bz_[b] = 0ull; bin_[b] = 0ull; bhn_[b] = 0ull; }
        #pragma unroll 8
        for (int k4 = k0; k4 < k0 + 32; k4++) {
            ulonglong2 ur = P1r[k4 * 256];
            ulonglong2 uz = P1z[k4 * 256];
            ulonglong2 un = P1n[k4 * 256];
            ulonglong2 vr = P2r[k4 * 256];
            ulonglong2 vz = P2z[k4 * 256];
            ulonglong2 vn = P2n[k4 * 256];
            #pragma unroll
            for (int b = 0; b < MB; b++) {
                ulonglong2 u = *(const ulonglong2*)&h0n[b * 256 + k4 * 4];
                fma2v(br_[b], ur, u); fma2v(bz_[b], uz, u); fma2v(bin_[b], un, u);
                ulonglong2 h = *(const ulonglong2*)&h1c[b * 256 + k4 * 4];
                fma2v(br_[b], vr, h); fma2v(bz_[b], vz, h); fma2v(bhn_[b], vn, h);
            }
        }
        if (ks) {
            #pragma unroll
            for (int b = 0; b < MB; b++) {
                red[(0 * 8 + b) * 128 + jl] = psum(br_[b]);
                red[(1 * 8 + b) * 128 + jl] = psum(bz_[b]);
                red[(2 * 8 + b) * 128 + jl] = psum(bin_[b]);
                red[(3 * 8 + b) * 128 + jl] = psum(bhn_[b]);
            }
        }
        __syncthreads();
        if (!ks) {
            #pragma unroll
            for (int b = 0; b < MB; b++) {
                float sr = psum(br_[b])  + red[(0 * 8 + b) * 128 + jl];
                float sz = psum(bz_[b])  + red[(1 * 8 + b) * 128 + jl];
                float si = psum(bin_[b]) + red[(2 * 8 + b) * 128 + jl];
                float sh = psum(bhn_[b]) + red[(3 * 8 + b) * 128 + jl];
                float rg = sigm(sr + c1r);
                float zg = sigm(sz + c1z);
                float n  = tanhe(si + c1in + rg * (sh + c1hn));
                float hn = (1.f - zg) * n + zg * h1c[b * 256 + j];
                h1n[b * 256 + j] = hn;
                st_cluster(rem_base + (u32)(OFF_H1 + (s ^ 1) * 2048 + b * 256 + j) * 4u, hn);
            }
        }
        cluster_sync();
        s ^= 1;
    }

    // z = tanh(h1_final @ fce_w.T + fce_b); each CTA does 4 of its 8 rows
    {
        const float* h1f = h1b + s * 2048;
        const int l  = tid & (LATD - 1);
        const int b0 = (int)rank * 4 + (tid >> 7) * 2;
        const float* wl = fce_w + (size_t)l * HH;
        for (int b = b0; b < b0 + 2; b++) {
            float acc = 0.f;
            #pragma unroll 8
            for (int k = 0; k < HH; k++) acc += wl[k] * h1f[b * 256 + k];
            float zz = tanhf(acc + fce_b[l]);
            g_z[(size_t)(base + b) * LATD + l] = zz;
            if (write_zout) z_out[(size_t)(base + b) * LATD + l] = zz;
        }
    }
    cluster_sync();
}

// ---------------------------------------------------------------------------
// Decoder
// ---------------------------------------------------------------------------
__global__ __launch_bounds__(NTH, 1) __cluster_dims__(2, 1, 1)
void dec_kernel(const float* __restrict__ Wih0,
                const float* __restrict__ bih0, const float* __restrict__ bhh0,
                const float* __restrict__ bih1, const float* __restrict__ bhh1,
                const float* __restrict__ fcd_w, const float* __restrict__ fcd_b,
                const float* __restrict__ fco_w, const float* __restrict__ fco_b,
                float* __restrict__ out)
{
    extern __shared__ __align__(16) float sm[];
    float* h0b = sm + OFF_H0;
    float* h1b = sm + OFF_H1;
    float* red = sm + OFF_RED;
    __shared__ float yb[MB][2];

    const int tid  = threadIdx.x;
    const int jl   = tid & 127;
    const int ks   = tid >> 7;
    const u32 rank = ctarank();
    const int j    = (int)rank * 128 + jl;
    const int base = (blockIdx.x >> 1) * MB;
    const int w    = tid >> 5;
    const int lane = tid & 31;

    // Init full h replica from fc_dec(z), raw row-major reshape:
    // dec_h[l][gb][u] = fcd_b[c'] + z[l*256+gb/2].fcd_w[c'], c' = (gb&1)*256+u
    {
        const int u = tid;
        #pragma unroll
        for (int b = 0; b < MB; b++) {
            int gb = base + b;
            int cr = ((gb & 1) << 8) + u;
            const float* wrow = fcd_w + (size_t)cr * LATD;
            const float* z0 = g_z + (size_t)(gb >> 1) * LATD;
            const float* z1 = g_z + (size_t)(256 + (gb >> 1)) * LATD;
            float a0 = fcd_b[cr], a1 = a0;
            #pragma unroll 8
            for (int k = 0; k < LATD; k++) {
                float wv = wrow[k];
                a0 += wv * z0[k];
                a1 += wv * z1[k];
            }
            h0b[b * 256 + u] = a0;
            h1b[b * 256 + u] = a1;
        }
    }
    if (tid < MB * 2) yb[tid >> 1][tid & 1] = 0.f;
    __syncthreads();

    const float d0wr0 = Wih0[j * 2 + 0],            d0wr1 = Wih0[j * 2 + 1];
    const float d0wz0 = Wih0[(HH + j) * 2 + 0],     d0wz1 = Wih0[(HH + j) * 2 + 1];
    const float d0wn0 = Wih0[(2 * HH + j) * 2 + 0], d0wn1 = Wih0[(2 * HH + j) * 2 + 1];
    const float c0r  = bih0[j] + bhh0[j];
    const float c0z  = bih0[HH + j] + bhh0[HH + j];
    const float c0in = bih0[2 * HH + j];
    const float c0hn = bhh0[2 * HH + j];
    const float c1r  = bih1[j] + bhh1[j];
    const float c1z  = bih1[HH + j] + bhh1[HH + j];
    const float c1in = bih1[2 * HH + j];
    const float c1hn = bhh1[2 * HH + j];

    const ulonglong2* P0r = g_Wp + (size_t) 9 * 16384 + j;
    const ulonglong2* P0z = g_Wp + (size_t)10 * 16384 + j;
    const ulonglong2* P0n = g_Wp + (size_t)11 * 16384 + j;
    const ulonglong2* P1r = g_Wp + (size_t)12 * 16384 + j;
    const ulonglong2* P1z = g_Wp + (size_t)13 * 16384 + j;
    const ulonglong2* P1n = g_Wp + (size_t)14 * 16384 + j;
    const ulonglong2* P2r = g_Wp + (size_t)15 * 16384 + j;
    const ulonglong2* P2z = g_Wp + (size_t)16 * 16384 + j;
    const ulonglong2* P2n = g_Wp + (size_t)17 * 16384 + j;

    const u32 loc_base = smem_u32(sm);
    const u32 rem_base = mapa_rank(loc_base, rank ^ 1);
    const int k0 = ks * 32;
    cluster_sync();

    int s = 0;
    for (int t = 0; t < TT; t++) {
        const float* h0c = h0b + s * 2048;
        float*       h0n = h0b + (s ^ 1) * 2048;
        const float* h1c = h1b + s * 2048;
        float*       h1n = h1b + (s ^ 1) * 2048;

        // ---- layer 0 matvec (unroll 16) ----
        ull ar[MB], az[MB], an_[MB];
        #pragma unroll
        for (int b = 0; b < MB; b++) { ar[b] = 0ull; az[b] = 0ull; an_[b] = 0ull; }
        #pragma unroll 16
        for (int k4 = k0; k4 < k0 + 32; k4++) {
            ulonglong2 wr = P0r[k4 * 256];
            ulonglong2 wz = P0z[k4 * 256];
            ulonglong2 wn = P0n[k4 * 256];
            #pragma unroll
            for (int b = 0; b < MB; b++) {
                ulonglong2 h = *(const ulonglong2*)&h0c[b * 256 + k4 * 4];
                fma2v(ar[b], wr, h); fma2v(az[b], wz, h); fma2v(an_[b], wn, h);
            }
        }
        if (ks) {
            #pragma unroll
            for (int b = 0; b < MB; b++) {
                red[(0 * 8 + b) * 128 + jl] = psum(ar[b]);
                red[(1 * 8 + b) * 128 + jl] = psum(az[b]);
                red[(2 * 8 + b) * 128 + jl] = psum(an_[b]);
            }
        }
        __syncthreads();
        if (!ks) {
            #pragma unroll
            for (int b = 0; b < MB; b++) {
                float sr = psum(ar[b])  + red[(0 * 8 + b) * 128 + jl];
                float sz = psum(az[b])  + red[(1 * 8 + b) * 128 + jl];
                float sn = psum(an_[b]) + red[(2 * 8 + b) * 128 + jl];
                float x0 = yb[b][0], x1 = yb[b][1];
                float rg = sigm(sr + c0r + d0wr0 * x0 + d0wr1 * x1);
                float zg = sigm(sz + c0z + d0wz0 * x0 + d0wz1 * x1);
                float n  = tanhe(c0in + d0wn0 * x0 + d0wn1 * x1 + rg * (sn + c0hn));
                float hn = (1.f - zg) * n + zg * h0c[b * 256 + j];
                h0n[b * 256 + j] = hn;
                st_cluster(rem_base + (u32)(OFF_H0 + (s ^ 1) * 2048 + b * 256 + j) * 4u, hn);
            }
        }
        cluster_sync();

        // ---- layer 1 fused (unroll 8) ----
        ull br_[MB], bz_[MB], bin_[MB], bhn_[MB];
        #pragma unroll
        for (int b = 0; b < MB; b++) { br_[b] = 0ull; bz_[b] = 0ull; bin_[b] = 0ull; bhn_[b] = 0ull; }
        #pragma unroll 8
        for (int k4 = k0; k4 < k0 + 32; k4++) {
            ulonglong2 ur = P1r[k4 * 256];
            ulonglong2 uz = P1z[k4 * 256];
            ulonglong2 un = P1n[k4 * 256];
            ulonglong2 vr = P2r[k4 * 256];
            ulonglong2 vz = P2z[k4 * 256];
            ulonglong2 vn = P2n[k4 * 256];
            #pragma unroll
            for (int b = 0; b < MB; b++) {
                ulonglong2 u = *(const ulonglong2*)&h0n[b * 256 + k4 * 4];
                fma2v(br_[b], ur, u); fma2v(bz_[b], uz, u); fma2v(bin_[b], un, u);
                ulonglong2 h = *(const ulonglong2*)&h1c[b * 256 + k4 * 4];
                fma2v(br_[b], vr, h); fma2v(bz_[b], vz, h); fma2v(bhn_[b], vn, h);
            }
        }
        if (ks) {
            #pragma unroll
            for (int b = 0; b < MB; b++) {
                red[(0 * 8 + b) * 128 + jl] = psum(br_[b]);
                red[(1 * 8 + b) * 128 + jl] = psum(bz_[b]);
                red[(2 * 8 + b) * 128 + jl] = psum(bin_[b]);
                red[(3 * 8 + b) * 128 + jl] = psum(bhn_[b]);
            }
        }
        __syncthreads();
        if (!ks) {
            #pragma unroll
            for (int b = 0; b < MB; b++) {
                float sr = psum(br_[b])  + red[(0 * 8 + b) * 128 + jl];
                float sz = psum(bz_[b])  + red[(1 * 8 + b) * 128 + jl];
                float si = psum(bin_[b]) + red[(2 * 8 + b) * 128 + jl];
                float sh = psum(bhn_[b]) + red[(3 * 8 + b) * 128 + jl];
                float rg = sigm(sr + c1r);
                float zg = sigm(sz + c1z);
                float n  = tanhe(si + c1in + rg * (sh + c1hn));
                float hn = (1.f - zg) * n + zg * h1c[b * 256 + j];
                h1n[b * 256 + j] = hn;
                st_cluster(rem_base + (u32)(OFF_H1 + (s ^ 1) * 2048 + b * 256 + j) * 4u, hn);
            }
        }
        cluster_sync();

        // ---- output head: warps 0..7 -> rows 0..7 (full h1n valid now) ----
        {
            const int b = w;
            float a0 = 0.f, a1 = 0.f;
            const float* w0 = fco_w;
            const float* w1 = fco_w + HH;
            #pragma unroll
            for (int k = lane; k < HH; k += 32) {
                float hv = h1n[b * 256 + k];
                a0 += w0[k] * hv;
                a1 += w1[k] * hv;
            }
            #pragma unroll
            for (int o = 16; o > 0; o >>= 1) {
                a0 += __shfl_xor_sync(0xffffffffu, a0, o);
                a1 += __shfl_xor_sync(0xffffffffu, a1, o);
            }
            if (lane == 0) {
                float y0 = a0 + fco_b[0];
                float y1 = a1 + fco_b[1];
                yb[b][0] = y0;
                yb[b][1] = y1;
                if (rank == 0) {
                    int gb = base + b;
                    out[((size_t)gb * TT + t) * 2 + 0] = y0;
                    out[((size_t)gb * TT + t) * 2 + 1] = y1;
                }
            }
        }
        __syncthreads();
        s ^= 1;
    }
    cluster_sync();
}

// ---------------------------------------------------------------------------
extern "C" void kernel_launch(void* const* d_in, const int* in_sizes, int n_in,
                              void* d_out, int out_size) {
    const float* x        = (const float*)d_in[0];
    const float* ln_w     = (const float*)d_in[1];
    const float* ln_b     = (const float*)d_in[2];
    const float* enc_Wih0 = (const float*)d_in[3];
    const float* enc_Whh0 = (const float*)d_in[4];
    const float* enc_bih0 = (const float*)d_in[5];
    const float* enc_bhh0 = (const float*)d_in[6];
    const float* enc_Wih1 = (const float*)d_in[7];
    const float* enc_Whh1 = (const float*)d_in[8];
    const float* enc_bih1 = (const float*)d_in[9];
    const float* enc_bhh1 = (const float*)d_in[10];
    const float* dec_Wih0 = (const float*)d_in[11];
    const float* dec_Whh0 = (const float*)d_in[12];
    const float* dec_bih0 = (const float*)d_in[13];
    const float* dec_bhh0 = (const float*)d_in[14];
    const float* dec_Wih1 = (const float*)d_in[15];
    const float* dec_Whh1 = (const float*)d_in[16];
    const float* dec_bih1 = (const float*)d_in[17];
    const float* dec_bhh1 = (const float*)d_in[18];
    const float* fc_enc_w = (const float*)d_in[19];
    const float* fc_enc_b = (const float*)d_in[20];
    const float* fc_dec_w = (const float*)d_in[21];
    const float* fc_dec_b = (const float*)d_in[22];
    const float* fc_out_w = (const float*)d_in[23];
    const float* fc_out_b = (const float*)d_in[24];

    float* out = (float*)d_out;
    const int recon_elems = BB * TT * 2;             // 184320
    const int z_elems     = BB * LATD;               // 65536
    int write_z = (out_size >= recon_elems + z_elems) ? 1 : 0;
    float* z_out = out + recon_elems;

    static int attr_done = 0;
    if (!attr_done) {
        cudaFuncSetAttribute(enc_kernel, cudaFuncAttributeMaxDynamicSharedMemorySize,
                             ENC_SMEM_FLOATS * 4);
        cudaFuncSetAttribute(dec_kernel, cudaFuncAttributeMaxDynamicSharedMemorySize,
                             DEC_SMEM_FLOATS * 4);
        attr_done = 1;
    }

    pack_kernel<<<6 * 192, 256>>>(enc_Whh0, enc_Wih1, enc_Whh1,
                                  dec_Whh0, dec_Wih1, dec_Whh1);

    enc_kernel<<<NB2, NTH, ENC_SMEM_FLOATS * 4>>>(
        x, ln_w, ln_b, enc_Wih0, enc_bih0, enc_bhh0,
        enc_bih1, enc_bhh1, fc_enc_w, fc_enc_b, z_out, write_z);

    dec_kernel<<<NB2, NTH, DEC_SMEM_FLOATS * 4>>>(
        dec_Wih0, dec_bih0, dec_bhh0, dec_bih1, dec_bhh1,
        fc_dec_w, fc_dec_b, fc_out_w, fc_out_b, out);
}

// round 16
// speedup vs baseline: 1.3578x; 1.0387x over previous
#include <cuda_runtime.h>
#include <cuda_bf16.h>
#include <cstdint>

// RNN autoencoder (GRU enc/dec) v12 = v11 (R15, 6306us) with layer-0 k-loop
// unroll 32 (full) and layer-1 k-loop unroll 16 (same proven knob, both
// loops; everything else identical).
// 128 blocks (64 clusters x 2); cluster owns MB=8 batch rows, CTA `rank`
// owns hidden units [rank*128, rank*128+128). 256 threads: jl = tid&127,
// ks = tid>>7 (k-half). Partials via SMEM red (ks=1 donates, ks=0
// finalizes); fused 6-stream layer-1 loop; two plain cluster_syncs per step.

#define TT   180
#define HH   256
#define BB   512
#define LATD 128
#define MB   8
#define NB2  128
#define NTH  256

typedef unsigned long long ull;
typedef unsigned int u32;

__device__ ulonglong2 g_Wp[6 * 3 * 64 * 256];
__device__ float g_z[BB * LATD];

__device__ __forceinline__ void fma2(ull& acc, ull a, ull b) {
    asm("fma.rn.f32x2 %0, %1, %2, %0;" : "+l"(acc) : "l"(a), "l"(b));
}
__device__ __forceinline__ void fma2v(ull& acc, ulonglong2 w, ulonglong2 h) {
    fma2(acc, w.x, h.x); fma2(acc, w.y, h.y);
}
__device__ __forceinline__ float psum(ull a) {
    float lo, hi;
    asm("mov.b64 {%0, %1}, %2;" : "=f"(lo), "=f"(hi) : "l"(a));
    return lo + hi;
}
__device__ __forceinline__ float sigm(float x) {
    return __fdividef(1.f, 1.f + __expf(-x));
}
__device__ __forceinline__ float tanhe(float x) {
    return 1.f - __fdividef(2.f, __expf(2.f * x) + 1.f);
}
__device__ __forceinline__ u32 smem_u32(const void* p) {
    u32 a;
    asm("{ .reg .u64 t; cvta.to.shared.u64 t, %1; cvt.u32.u64 %0, t; }"
        : "=r"(a) : "l"(p));
    return a;
}
__device__ __forceinline__ u32 mapa_rank(u32 a, u32 r) {
    u32 o;
    asm("mapa.shared::cluster.u32 %0, %1, %2;" : "=r"(o) : "r"(a), "r"(r));
    return o;
}
__device__ __forceinline__ void st_cluster(u32 a, float v) {
    asm volatile("st.shared::cluster.f32 [%0], %1;" :: "r"(a), "f"(v) : "memory");
}
__device__ __forceinline__ void cluster_sync() {
    asm volatile("barrier.cluster.arrive.aligned;" ::: "memory");
    asm volatile("barrier.cluster.wait.aligned;" ::: "memory");
}
__device__ __forceinline__ u32 ctarank() {
    u32 r; asm("mov.u32 %0, %%cluster_ctarank;" : "=r"(r)); return r;
}

// ---------------------------------------------------------------------------
__global__ void pack_kernel(const float* __restrict__ W0, const float* __restrict__ W1,
                            const float* __restrict__ W2, const float* __restrict__ W3,
                            const float* __restrict__ W4, const float* __restrict__ W5)
{
    int m  = blockIdx.x / 192;
    int r  = blockIdx.x % 192;
    int g  = r >> 6;
    int k4 = r & 63;
    int j  = threadIdx.x;
    const float* W = W0;
    if (m == 1) W = W1; else if (m == 2) W = W2;
    else if (m == 3) W = W3; else if (m == 4) W = W4; else if (m == 5) W = W5;
    const float* row = W + (size_t)(g * 256 + j) * 256 + k4 * 4;
    float4 v = make_float4(row[0], row[1], row[2], row[3]);
    g_Wp[(size_t)((m * 3 + g) * 64 + k4) * 256 + j] = *(ulonglong2*)&v;
}

// Shared layout (floats): h0[2][8][256] @0, h1[2][8][256] @4096,
// red[32][128] @8192, (enc) x[8][180][2] @12288
#define OFF_H0  0
#define OFF_H1  4096
#define OFF_RED 8192
#define OFF_X   12288
#define ENC_SMEM_FLOATS (12288 + MB * TT * 2)
#define DEC_SMEM_FLOATS 12288

// ---------------------------------------------------------------------------
// Encoder
// ---------------------------------------------------------------------------
__global__ __launch_bounds__(NTH, 1) __cluster_dims__(2, 1, 1)
void enc_kernel(const float* __restrict__ x,
                const float* __restrict__ ln_w, const float* __restrict__ ln_b,
                const float* __restrict__ Wih0,
                const float* __restrict__ bih0, const float* __restrict__ bhh0,
                const float* __restrict__ bih1, const float* __restrict__ bhh1,
                const float* __restrict__ fce_w, const float* __restrict__ fce_b,
                float* __restrict__ z_out, int write_zout)
{
    extern __shared__ __align__(16) float sm[];
    float* h0b = sm + OFF_H0;
    float* h1b = sm + OFF_H1;
    float* red = sm + OFF_RED;
    float* xb  = sm + OFF_X;

    const int tid  = threadIdx.x;
    const int jl   = tid & 127;
    const int ks   = tid >> 7;
    const u32 rank = ctarank();
    const int j    = (int)rank * 128 + jl;
    const int base = (blockIdx.x >> 1) * MB;
    const int w    = tid >> 5;
    const int lane = tid & 31;

    for (int i = tid; i < 4096; i += NTH) { h0b[i] = 0.f; h1b[i] = 0.f; }

    // LayerNorm per batch row (warps 0..7 -> rows 0..7)
    {
        const int b = w;
        const float* xr = x + (size_t)(base + b) * TT * 2;
        float s = 0.f, s2 = 0.f;
        for (int i = lane; i < TT * 2; i += 32) {
            float v = xr[i]; s += v; s2 += v * v;
        }
        #pragma unroll
        for (int o = 16; o > 0; o >>= 1) {
            s  += __shfl_xor_sync(0xffffffffu, s, o);
            s2 += __shfl_xor_sync(0xffffffffu, s2, o);
        }
        const float inv = 1.f / (TT * 2);
        float mu  = s * inv;
        float var = s2 * inv - mu * mu;
        float rs  = rsqrtf(var + 1e-5f);
        for (int i = lane; i < TT * 2; i += 32)
            xb[b * TT * 2 + i] = (xr[i] - mu) * rs * ln_w[i] + ln_b[i];
    }
    __syncthreads();

    const float e0wr0 = Wih0[j * 2 + 0],            e0wr1 = Wih0[j * 2 + 1];
    const float e0wz0 = Wih0[(HH + j) * 2 + 0],     e0wz1 = Wih0[(HH + j) * 2 + 1];
    const float e0wn0 = Wih0[(2 * HH + j) * 2 + 0], e0wn1 = Wih0[(2 * HH + j) * 2 + 1];
    const float c0r  = bih0[j] + bhh0[j];
    const float c0z  = bih0[HH + j] + bhh0[HH + j];
    const float c0in = bih0[2 * HH + j];
    const float c0hn = bhh0[2 * HH + j];
    const float c1r  = bih1[j] + bhh1[j];
    const float c1z  = bih1[HH + j] + bhh1[HH + j];
    const float c1in = bih1[2 * HH + j];
    const float c1hn = bhh1[2 * HH + j];

    const ulonglong2* P0r = g_Wp + (size_t)0 * 16384 + j;
    const ulonglong2* P0z = g_Wp + (size_t)1 * 16384 + j;
    const ulonglong2* P0n = g_Wp + (size_t)2 * 16384 + j;
    const ulonglong2* P1r = g_Wp + (size_t)3 * 16384 + j;
    const ulonglong2* P1z = g_Wp + (size_t)4 * 16384 + j;
    const ulonglong2* P1n = g_Wp + (size_t)5 * 16384 + j;
    const ulonglong2* P2r = g_Wp + (size_t)6 * 16384 + j;
    const ulonglong2* P2z = g_Wp + (size_t)7 * 16384 + j;
    const ulonglong2* P2n = g_Wp + (size_t)8 * 16384 + j;

    const u32 loc_base = smem_u32(sm);
    const u32 rem_base = mapa_rank(loc_base, rank ^ 1);
    const int k0 = ks * 32;
    cluster_sync();

    int s = 0;
    for (int t = 0; t < TT; t++) {
        const float* h0c = h0b + s * 2048;
        float*       h0n = h0b + (s ^ 1) * 2048;
        const float* h1c = h1b + s * 2048;
        float*       h1n = h1b + (s ^ 1) * 2048;

        // ---- layer 0 matvec over this thread's k-half (full unroll) ----
        ull ar[MB], az[MB], an_[MB];
        #pragma unroll
        for (int b = 0; b < MB; b++) { ar[b] = 0ull; az[b] = 0ull; an_[b] = 0ull; }
        #pragma unroll 32
        for (int k4 = k0; k4 < k0 + 32; k4++) {
            ulonglong2 wr = P0r[k4 * 256];
            ulonglong2 wz = P0z[k4 * 256];
            ulonglong2 wn = P0n[k4 * 256];
            #pragma unroll
            for (int b = 0; b < MB; b++) {
                ulonglong2 h = *(const ulonglong2*)&h0c[b * 256 + k4 * 4];
                fma2v(ar[b], wr, h); fma2v(az[b], wz, h); fma2v(an_[b], wn, h);
            }
        }
        if (ks) {
            #pragma unroll
            for (int b = 0; b < MB; b++) {
                red[(0 * 8 + b) * 128 + jl] = psum(ar[b]);
                red[(1 * 8 + b) * 128 + jl] = psum(az[b]);
                red[(2 * 8 + b) * 128 + jl] = psum(an_[b]);
            }
        }
        __syncthreads();
        if (!ks) {
            #pragma unroll
            for (int b = 0; b < MB; b++) {
                float sr = psum(ar[b])  + red[(0 * 8 + b) * 128 + jl];
                float sz = psum(az[b])  + red[(1 * 8 + b) * 128 + jl];
                float sn = psum(an_[b]) + red[(2 * 8 + b) * 128 + jl];
                float x0 = xb[b * TT * 2 + t * 2 + 0];
                float x1 = xb[b * TT * 2 + t * 2 + 1];
                float rg = sigm(sr + c0r + e0wr0 * x0 + e0wr1 * x1);
                float zg = sigm(sz + c0z + e0wz0 * x0 + e0wz1 * x1);
                float n  = tanhe(c0in + e0wn0 * x0 + e0wn1 * x1 + rg * (sn + c0hn));
                float hn = (1.f - zg) * n + zg * h0c[b * 256 + j];
                h0n[b * 256 + j] = hn;
                st_cluster(rem_base + (u32)(OFF_H0 + (s ^ 1) * 2048 + b * 256 + j) * 4u, hn);
            }
        }
        cluster_sync();

        // ---- layer 1 fused: gi = Wih1 @ h0n, gh = Whh1 @ h1c (unroll 16) ----
        ull br_[MB], bz_[MB], bin_[MB], bhn_[MB];
        #pragma unroll
        for (int b = 0; b < MB; b++) { br_[b] = 0ull; bz_[b] = 0ull; bin_[b] = 0ull; bhn_[b] = 0ull; }
        #pragma unroll 16
        for (int k4 = k0; k4 < k0 + 32; k4++) {
            ulonglong2 ur = P1r[k4 * 256];
            ulonglong2 uz = P1z[k4 * 256];
            ulonglong2 un = P1n[k4 * 256];
            ulonglong2 vr = P2r[k4 * 256];
            ulonglong2 vz = P2z[k4 * 256];
            ulonglong2 vn = P2n[k4 * 256];
            #pragma unroll
            for (int b = 0; b < MB; b++) {
                ulonglong2 u = *(const ulonglong2*)&h0n[b * 256 + k4 * 4];
                fma2v(br_[b], ur, u); fma2v(bz_[b], uz, u); fma2v(bin_[b], un, u);
                ulonglong2 h = *(const ulonglong2*)&h1c[b * 256 + k4 * 4];
                fma2v(br_[b], vr, h); fma2v(bz_[b], vz, h); fma2v(bhn_[b], vn, h);
            }
        }
        if (ks) {
            #pragma unroll
            for (int b = 0; b < MB; b++) {
                red[(0 * 8 + b) * 128 + jl] = psum(br_[b]);
                red[(1 * 8 + b) * 128 + jl] = psum(bz_[b]);
                red[(2 * 8 + b) * 128 + jl] = psum(bin_[b]);
                red[(3 * 8 + b) * 128 + jl] = psum(bhn_[b]);
            }
        }
        __syncthreads();
        if (!ks) {
            #pragma unroll
            for (int b = 0; b < MB; b++) {
                float sr = psum(br_[b])  + red[(0 * 8 + b) * 128 + jl];
                float sz = psum(bz_[b])  + red[(1 * 8 + b) * 128 + jl];
                float si = psum(bin_[b]) + red[(2 * 8 + b) * 128 + jl];
                float sh = psum(bhn_[b]) + red[(3 * 8 + b) * 128 + jl];
                float rg = sigm(sr + c1r);
                float zg = sigm(sz + c1z);
                float n  = tanhe(si + c1in + rg * (sh + c1hn));
                float hn = (1.f - zg) * n + zg * h1c[b * 256 + j];
                h1n[b * 256 + j] = hn;
                st_cluster(rem_base + (u32)(OFF_H1 + (s ^ 1) * 2048 + b * 256 + j) * 4u, hn);
            }
        }
        cluster_sync();
        s ^= 1;
    }

    // z = tanh(h1_final @ fce_w.T + fce_b); each CTA does 4 of its 8 rows
    {
        const float* h1f = h1b + s * 2048;
        const int l  = tid & (LATD - 1);
        const int b0 = (int)rank * 4 + (tid >> 7) * 2;
        const float* wl = fce_w + (size_t)l * HH;
        for (int b = b0; b < b0 + 2; b++) {
            float acc = 0.f;
            #pragma unroll 8
            for (int k = 0; k < HH; k++) acc += wl[k] * h1f[b * 256 + k];
            float zz = tanhf(acc + fce_b[l]);
            g_z[(size_t)(base + b) * LATD + l] = zz;
            if (write_zout) z_out[(size_t)(base + b) * LATD + l] = zz;
        }
    }
    cluster_sync();
}

// ---------------------------------------------------------------------------
// Decoder
// ---------------------------------------------------------------------------
__global__ __launch_bounds__(NTH, 1) __cluster_dims__(2, 1, 1)
void dec_kernel(const float* __restrict__ Wih0,
                const float* __restrict__ bih0, const float* __restrict__ bhh0,
                const float* __restrict__ bih1, const float* __restrict__ bhh1,
                const float* __restrict__ fcd_w, const float* __restrict__ fcd_b,
                const float* __restrict__ fco_w, const float* __restrict__ fco_b,
                float* __restrict__ out)
{
    extern __shared__ __align__(16) float sm[];
    float* h0b = sm + OFF_H0;
    float* h1b = sm + OFF_H1;
    float* red = sm + OFF_RED;
    __shared__ float yb[MB][2];

    const int tid  = threadIdx.x;
    const int jl   = tid & 127;
    const int ks   = tid >> 7;
    const u32 rank = ctarank();
    const int j    = (int)rank * 128 + jl;
    const int base = (blockIdx.x >> 1) * MB;
    const int w    = tid >> 5;
    const int lane = tid & 31;

    // Init full h replica from fc_dec(z), raw row-major reshape:
    // dec_h[l][gb][u] = fcd_b[c'] + z[l*256+gb/2].fcd_w[c'], c' = (gb&1)*256+u
    {
        const int u = tid;
        #pragma unroll
        for (int b = 0; b < MB; b++) {
            int gb = base + b;
            int cr = ((gb & 1) << 8) + u;
            const float* wrow = fcd_w + (size_t)cr * LATD;
            const float* z0 = g_z + (size_t)(gb >> 1) * LATD;
            const float* z1 = g_z + (size_t)(256 + (gb >> 1)) * LATD;
            float a0 = fcd_b[cr], a1 = a0;
            #pragma unroll 8
            for (int k = 0; k < LATD; k++) {
                float wv = wrow[k];
                a0 += wv * z0[k];
                a1 += wv * z1[k];
            }
            h0b[b * 256 + u] = a0;
            h1b[b * 256 + u] = a1;
        }
    }
    if (tid < MB * 2) yb[tid >> 1][tid & 1] = 0.f;
    __syncthreads();

    const float d0wr0 = Wih0[j * 2 + 0],            d0wr1 = Wih0[j * 2 + 1];
    const float d0wz0 = Wih0[(HH + j) * 2 + 0],     d0wz1 = Wih0[(HH + j) * 2 + 1];
    const float d0wn0 = Wih0[(2 * HH + j) * 2 + 0], d0wn1 = Wih0[(2 * HH + j) * 2 + 1];
    const float c0r  = bih0[j] + bhh0[j];
    const float c0z  = bih0[HH + j] + bhh0[HH + j];
    const float c0in = bih0[2 * HH + j];
    const float c0hn = bhh0[2 * HH + j];
    const float c1r  = bih1[j] + bhh1[j];
    const float c1z  = bih1[HH + j] + bhh1[HH + j];
    const float c1in = bih1[2 * HH + j];
    const float c1hn = bhh1[2 * HH + j];

    const ulonglong2* P0r = g_Wp + (size_t) 9 * 16384 + j;
    const ulonglong2* P0z = g_Wp + (size_t)10 * 16384 + j;
    const ulonglong2* P0n = g_Wp + (size_t)11 * 16384 + j;
    const ulonglong2* P1r = g_Wp + (size_t)12 * 16384 + j;
    const ulonglong2* P1z = g_Wp + (size_t)13 * 16384 + j;
    const ulonglong2* P1n = g_Wp + (size_t)14 * 16384 + j;
    const ulonglong2* P2r = g_Wp + (size_t)15 * 16384 + j;
    const ulonglong2* P2z = g_Wp + (size_t)16 * 16384 + j;
    const ulonglong2* P2n = g_Wp + (size_t)17 * 16384 + j;

    const u32 loc_base = smem_u32(sm);
    const u32 rem_base = mapa_rank(loc_base, rank ^ 1);
    const int k0 = ks * 32;
    cluster_sync();

    int s = 0;
    for (int t = 0; t < TT; t++) {
        const float* h0c = h0b + s * 2048;
        float*       h0n = h0b + (s ^ 1) * 2048;
        const float* h1c = h1b + s * 2048;
        float*       h1n = h1b + (s ^ 1) * 2048;

        // ---- layer 0 matvec (full unroll) ----
        ull ar[MB], az[MB], an_[MB];
        #pragma unroll
        for (int b = 0; b < MB; b++) { ar[b] = 0ull; az[b] = 0ull; an_[b] = 0ull; }
        #pragma unroll 32
        for (int k4 = k0; k4 < k0 + 32; k4++) {
            ulonglong2 wr = P0r[k4 * 256];
            ulonglong2 wz = P0z[k4 * 256];
            ulonglong2 wn = P0n[k4 * 256];
            #pragma unroll
            for (int b = 0; b < MB; b++) {
                ulonglong2 h = *(const ulonglong2*)&h0c[b * 256 + k4 * 4];
                fma2v(ar[b], wr, h); fma2v(az[b], wz, h); fma2v(an_[b], wn, h);
            }
        }
        if (ks) {
            #pragma unroll
            for (int b = 0; b < MB; b++) {
                red[(0 * 8 + b) * 128 + jl] = psum(ar[b]);
                red[(1 * 8 + b) * 128 + jl] = psum(az[b]);
                red[(2 * 8 + b) * 128 + jl] = psum(an_[b]);
            }
        }
        __syncthreads();
        if (!ks) {
            #pragma unroll
            for (int b = 0; b < MB; b++) {
                float sr = psum(ar[b])  + red[(0 * 8 + b) * 128 + jl];
                float sz = psum(az[b])  + red[(1 * 8 + b) * 128 + jl];
                float sn = psum(an_[b]) + red[(2 * 8 + b) * 128 + jl];
                float x0 = yb[b][0], x1 = yb[b][1];
                float rg = sigm(sr + c0r + d0wr0 * x0 + d0wr1 * x1);
                float zg = sigm(sz + c0z + d0wz0 * x0 + d0wz1 * x1);
                float n  = tanhe(c0in + d0wn0 * x0 + d0wn1 * x1 + rg * (sn + c0hn));
                float hn = (1.f - zg) * n + zg * h0c[b * 256 + j];
                h0n[b * 256 + j] = hn;
                st_cluster(rem_base + (u32)(OFF_H0 + (s ^ 1) * 2048 + b * 256 + j) * 4u, hn);
            }
        }
        cluster_sync();

        // ---- layer 1 fused (unroll 16) ----
        ull br_[MB], bz_[MB], bin_[MB], bhn_[MB];
        #pragma unroll
        for (int b = 0; b < MB; b++) { br_[b] = 0ull; bz_[b] = 0ull; bin_[b] = 0ull; bhn_[b] = 0ull; }
        #pragma unroll 16
        for (int k4 = k0; k4 < k0 + 32; k4++) {
            ulonglong2 ur = P1r[k4 * 256];
            ulonglong2 uz = P1z[k4 * 256];
            ulonglong2 un = P1n[k4 * 256];
            ulonglong2 vr = P2r[k4 * 256];
            ulonglong2 vz = P2z[k4 * 256];
            ulonglong2 vn = P2n[k4 * 256];
            #pragma unroll
            for (int b = 0; b < MB; b++) {
                ulonglong2 u = *(const ulonglong2*)&h0n[b * 256 + k4 * 4];
                fma2v(br_[b], ur, u); fma2v(bz_[b], uz, u); fma2v(bin_[b], un, u);
                ulonglong2 h = *(const ulonglong2*)&h1c[b * 256 + k4 * 4];
                fma2v(br_[b], vr, h); fma2v(bhn_[b], vn, h); fma2v(bz_[b], vz, h);
            }
        }
        if (ks) {
            #pragma unroll
            for (int b = 0; b < MB; b++) {
                red[(0 * 8 + b) * 128 + jl] = psum(br_[b]);
                red[(1 * 8 + b) * 128 + jl] = psum(bz_[b]);
                red[(2 * 8 + b) * 128 + jl] = psum(bin_[b]);
                red[(3 * 8 + b) * 128 + jl] = psum(bhn_[b]);
            }
        }
        __syncthreads();
        if (!ks) {
            #pragma unroll
            for (int b = 0; b < MB; b++) {
                float sr = psum(br_[b])  + red[(0 * 8 + b) * 128 + jl];
                float sz = psum(bz_[b])  + red[(1 * 8 + b) * 128 + jl];
                float si = psum(bin_[b]) + red[(2 * 8 + b) * 128 + jl];
                float sh = psum(bhn_[b]) + red[(3 * 8 + b) * 128 + jl];
                float rg = sigm(sr + c1r);
                float zg = sigm(sz + c1z);
                float n  = tanhe(si + c1in + rg * (sh + c1hn));
                float hn = (1.f - zg) * n + zg * h1c[b * 256 + j];
                h1n[b * 256 + j] = hn;
                st_cluster(rem_base + (u32)(OFF_H1 + (s ^ 1) * 2048 + b * 256 + j) * 4u, hn);
            }
        }
        cluster_sync();

        // ---- output head: warps 0..7 -> rows 0..7 (full h1n valid now) ----
        {
            const int b = w;
            float a0 = 0.f, a1 = 0.f;
            const float* w0 = fco_w;
            const float* w1 = fco_w + HH;
            #pragma unroll
            for (int k = lane; k < HH; k += 32) {
                float hv = h1n[b * 256 + k];
                a0 += w0[k] * hv;
                a1 += w1[k] * hv;
            }
            #pragma unroll
            for (int o = 16; o > 0; o >>= 1) {
                a0 += __shfl_xor_sync(0xffffffffu, a0, o);
                a1 += __shfl_xor_sync(0xffffffffu, a1, o);
            }
            if (lane == 0) {
                float y0 = a0 + fco_b[0];
                float y1 = a1 + fco_b[1];
                yb[b][0] = y0;
                yb[b][1] = y1;
                if (rank == 0) {
                    int gb = base + b;
                    out[((size_t)gb * TT + t) * 2 + 0] = y0;
                    out[((size_t)gb * TT + t) * 2 + 1] = y1;
                }
            }
        }
        __syncthreads();
        s ^= 1;
    }
    cluster_sync();
}

// ---------------------------------------------------------------------------
extern "C" void kernel_launch(void* const* d_in, const int* in_sizes, int n_in,
                              void* d_out, int out_size) {
    const float* x        = (const float*)d_in[0];
    const float* ln_w     = (const float*)d_in[1];
    const float* ln_b     = (const float*)d_in[2];
    const float* enc_Wih0 = (const float*)d_in[3];
    const float* enc_Whh0 = (const float*)d_in[4];
    const float* enc_bih0 = (const float*)d_in[5];
    const float* enc_bhh0 = (const float*)d_in[6];
    const float* enc_Wih1 = (const float*)d_in[7];
    const float* enc_Whh1 = (const float*)d_in[8];
    const float* enc_bih1 = (const float*)d_in[9];
    const float* enc_bhh1 = (const float*)d_in[10];
    const float* dec_Wih0 = (const float*)d_in[11];
    const float* dec_Whh0 = (const float*)d_in[12];
    const float* dec_bih0 = (const float*)d_in[13];
    const float* dec_bhh0 = (const float*)d_in[14];
    const float* dec_Wih1 = (const float*)d_in[15];
    const float* dec_Whh1 = (const float*)d_in[16];
    const float* dec_bih1 = (const float*)d_in[17];
    const float* dec_bhh1 = (const float*)d_in[18];
    const float* fc_enc_w = (const float*)d_in[19];
    const float* fc_enc_b = (const float*)d_in[20];
    const float* fc_dec_w = (const float*)d_in[21];
    const float* fc_dec_b = (const float*)d_in[22];
    const float* fc_out_w = (const float*)d_in[23];
    const float* fc_out_b = (const float*)d_in[24];

    float* out = (float*)d_out;
    const int recon_elems = BB * TT * 2;             // 184320
    const int z_elems     = BB * LATD;               // 65536
    int write_z = (out_size >= recon_elems + z_elems) ? 1 : 0;
    float* z_out = out + recon_elems;

    static int attr_done = 0;
    if (!attr_done) {
        cudaFuncSetAttribute(enc_kernel, cudaFuncAttributeMaxDynamicSharedMemorySize,
                             ENC_SMEM_FLOATS * 4);
        cudaFuncSetAttribute(dec_kernel, cudaFuncAttributeMaxDynamicSharedMemorySize,
                             DEC_SMEM_FLOATS * 4);
        attr_done = 1;
    }

    pack_kernel<<<6 * 192, 256>>>(enc_Whh0, enc_Wih1, enc_Whh1,
                                  dec_Whh0, dec_Wih1, dec_Whh1);

    enc_kernel<<<NB2, NTH, ENC_SMEM_FLOATS * 4>>>(
        x, ln_w, ln_b, enc_Wih0, enc_bih0, enc_bhh0,
        enc_bih1, enc_bhh1, fc_enc_w, fc_enc_b, z_out, write_z);

    dec_kernel<<<NB2, NTH, DEC_SMEM_FLOATS * 4>>>(
        dec_Wih0, dec_bih0, dec_bhh0, dec_bih1, dec_bhh1,
        fc_dec_w, fc_dec_b, fc_out_w, fc_out_b, out);
}

// round 17
// speedup vs baseline: 1.3801x; 1.0164x over previous
#include <cuda_runtime.h>
#include <cuda_bf16.h>
#include <cstdint>

// RNN autoencoder (GRU enc/dec) v13 = v12 (R16, 6071us) with layer-1 k-loop
// unroll 32 (full; ONLY change). Both matvec loops now fully unrolled.
// 128 blocks (64 clusters x 2); cluster owns MB=8 batch rows, CTA `rank`
// owns hidden units [rank*128, rank*128+128). 256 threads: jl = tid&127,
// ks = tid>>7 (k-half). Partials via SMEM red (ks=1 donates, ks=0
// finalizes); fused 6-stream layer-1 loop; two plain cluster_syncs per step.

#define TT   180
#define HH   256
#define BB   512
#define LATD 128
#define MB   8
#define NB2  128
#define NTH  256

typedef unsigned long long ull;
typedef unsigned int u32;

__device__ ulonglong2 g_Wp[6 * 3 * 64 * 256];
__device__ float g_z[BB * LATD];

__device__ __forceinline__ void fma2(ull& acc, ull a, ull b) {
    asm("fma.rn.f32x2 %0, %1, %2, %0;" : "+l"(acc) : "l"(a), "l"(b));
}
__device__ __forceinline__ void fma2v(ull& acc, ulonglong2 w, ulonglong2 h) {
    fma2(acc, w.x, h.x); fma2(acc, w.y, h.y);
}
__device__ __forceinline__ float psum(ull a) {
    float lo, hi;
    asm("mov.b64 {%0, %1}, %2;" : "=f"(lo), "=f"(hi) : "l"(a));
    return lo + hi;
}
__device__ __forceinline__ float sigm(float x) {
    return __fdividef(1.f, 1.f + __expf(-x));
}
__device__ __forceinline__ float tanhe(float x) {
    return 1.f - __fdividef(2.f, __expf(2.f * x) + 1.f);
}
__device__ __forceinline__ u32 smem_u32(const void* p) {
    u32 a;
    asm("{ .reg .u64 t; cvta.to.shared.u64 t, %1; cvt.u32.u64 %0, t; }"
        : "=r"(a) : "l"(p));
    return a;
}
__device__ __forceinline__ u32 mapa_rank(u32 a, u32 r) {
    u32 o;
    asm("mapa.shared::cluster.u32 %0, %1, %2;" : "=r"(o) : "r"(a), "r"(r));
    return o;
}
__device__ __forceinline__ void st_cluster(u32 a, float v) {
    asm volatile("st.shared::cluster.f32 [%0], %1;" :: "r"(a), "f"(v) : "memory");
}
__device__ __forceinline__ void cluster_sync() {
    asm volatile("barrier.cluster.arrive.aligned;" ::: "memory");
    asm volatile("barrier.cluster.wait.aligned;" ::: "memory");
}
__device__ __forceinline__ u32 ctarank() {
    u32 r; asm("mov.u32 %0, %%cluster_ctarank;" : "=r"(r)); return r;
}

// ---------------------------------------------------------------------------
__global__ void pack_kernel(const float* __restrict__ W0, const float* __restrict__ W1,
                            const float* __restrict__ W2, const float* __restrict__ W3,
                            const float* __restrict__ W4, const float* __restrict__ W5)
{
    int m  = blockIdx.x / 192;
    int r  = blockIdx.x % 192;
    int g  = r >> 6;
    int k4 = r & 63;
    int j  = threadIdx.x;
    const float* W = W0;
    if (m == 1) W = W1; else if (m == 2) W = W2;
    else if (m == 3) W = W3; else if (m == 4) W = W4; else if (m == 5) W = W5;
    const float* row = W + (size_t)(g * 256 + j) * 256 + k4 * 4;
    float4 v = make_float4(row[0], row[1], row[2], row[3]);
    g_Wp[(size_t)((m * 3 + g) * 64 + k4) * 256 + j] = *(ulonglong2*)&v;
}

// Shared layout (floats): h0[2][8][256] @0, h1[2][8][256] @4096,
// red[32][128] @8192, (enc) x[8][180][2] @12288
#define OFF_H0  0
#define OFF_H1  4096
#define OFF_RED 8192
#define OFF_X   12288
#define ENC_SMEM_FLOATS (12288 + MB * TT * 2)
#define DEC_SMEM_FLOATS 12288

// ---------------------------------------------------------------------------
// Encoder
// ---------------------------------------------------------------------------
__global__ __launch_bounds__(NTH, 1) __cluster_dims__(2, 1, 1)
void enc_kernel(const float* __restrict__ x,
                const float* __restrict__ ln_w, const float* __restrict__ ln_b,
                const float* __restrict__ Wih0,
                const float* __restrict__ bih0, const float* __restrict__ bhh0,
                const float* __restrict__ bih1, const float* __restrict__ bhh1,
                const float* __restrict__ fce_w, const float* __restrict__ fce_b,
                float* __restrict__ z_out, int write_zout)
{
    extern __shared__ __align__(16) float sm[];
    float* h0b = sm + OFF_H0;
    float* h1b = sm + OFF_H1;
    float* red = sm + OFF_RED;
    float* xb  = sm + OFF_X;

    const int tid  = threadIdx.x;
    const int jl   = tid & 127;
    const int ks   = tid >> 7;
    const u32 rank = ctarank();
    const int j    = (int)rank * 128 + jl;
    const int base = (blockIdx.x >> 1) * MB;
    const int w    = tid >> 5;
    const int lane = tid & 31;

    for (int i = tid; i < 4096; i += NTH) { h0b[i] = 0.f; h1b[i] = 0.f; }

    // LayerNorm per batch row (warps 0..7 -> rows 0..7)
    {
        const int b = w;
        const float* xr = x + (size_t)(base + b) * TT * 2;
        float s = 0.f, s2 = 0.f;
        for (int i = lane; i < TT * 2; i += 32) {
            float v = xr[i]; s += v; s2 += v * v;
        }
        #pragma unroll
        for (int o = 16; o > 0; o >>= 1) {
            s  += __shfl_xor_sync(0xffffffffu, s, o);
            s2 += __shfl_xor_sync(0xffffffffu, s2, o);
        }
        const float inv = 1.f / (TT * 2);
        float mu  = s * inv;
        float var = s2 * inv - mu * mu;
        float rs  = rsqrtf(var + 1e-5f);
        for (int i = lane; i < TT * 2; i += 32)
            xb[b * TT * 2 + i] = (xr[i] - mu) * rs * ln_w[i] + ln_b[i];
    }
    __syncthreads();

    const float e0wr0 = Wih0[j * 2 + 0],            e0wr1 = Wih0[j * 2 + 1];
    const float e0wz0 = Wih0[(HH + j) * 2 + 0],     e0wz1 = Wih0[(HH + j) * 2 + 1];
    const float e0wn0 = Wih0[(2 * HH + j) * 2 + 0], e0wn1 = Wih0[(2 * HH + j) * 2 + 1];
    const float c0r  = bih0[j] + bhh0[j];
    const float c0z  = bih0[HH + j] + bhh0[HH + j];
    const float c0in = bih0[2 * HH + j];
    const float c0hn = bhh0[2 * HH + j];
    const float c1r  = bih1[j] + bhh1[j];
    const float c1z  = bih1[HH + j] + bhh1[HH + j];
    const float c1in = bih1[2 * HH + j];
    const float c1hn = bhh1[2 * HH + j];

    const ulonglong2* P0r = g_Wp + (size_t)0 * 16384 + j;
    const ulonglong2* P0z = g_Wp + (size_t)1 * 16384 + j;
    const ulonglong2* P0n = g_Wp + (size_t)2 * 16384 + j;
    const ulonglong2* P1r = g_Wp + (size_t)3 * 16384 + j;
    const ulonglong2* P1z = g_Wp + (size_t)4 * 16384 + j;
    const ulonglong2* P1n = g_Wp + (size_t)5 * 16384 + j;
    const ulonglong2* P2r = g_Wp + (size_t)6 * 16384 + j;
    const ulonglong2* P2z = g_Wp + (size_t)7 * 16384 + j;
    const ulonglong2* P2n = g_Wp + (size_t)8 * 16384 + j;

    const u32 loc_base = smem_u32(sm);
    const u32 rem_base = mapa_rank(loc_base, rank ^ 1);
    const int k0 = ks * 32;
    cluster_sync();

    int s = 0;
    for (int t = 0; t < TT; t++) {
        const float* h0c = h0b + s * 2048;
        float*       h0n = h0b + (s ^ 1) * 2048;
        const float* h1c = h1b + s * 2048;
        float*       h1n = h1b + (s ^ 1) * 2048;

        // ---- layer 0 matvec over this thread's k-half (full unroll) ----
        ull ar[MB], az[MB], an_[MB];
        #pragma unroll
        for (int b = 0; b < MB; b++) { ar[b] = 0ull; az[b] = 0ull; an_[b] = 0ull; }
        #pragma unroll 32
        for (int k4 = k0; k4 < k0 + 32; k4++) {
            ulonglong2 wr = P0r[k4 * 256];
            ulonglong2 wz = P0z[k4 * 256];
            ulonglong2 wn = P0n[k4 * 256];
            #pragma unroll
            for (int b = 0; b < MB; b++) {
                ulonglong2 h = *(const ulonglong2*)&h0c[b * 256 + k4 * 4];
                fma2v(ar[b], wr, h); fma2v(az[b], wz, h); fma2v(an_[b], wn, h);
            }
        }
        if (ks) {
            #pragma unroll
            for (int b = 0; b < MB; b++) {
                red[(0 * 8 + b) * 128 + jl] = psum(ar[b]);
                red[(1 * 8 + b) * 128 + jl] = psum(az[b]);
                red[(2 * 8 + b) * 128 + jl] = psum(an_[b]);
            }
        }
        __syncthreads();
        if (!ks) {
            #pragma unroll
            for (int b = 0; b < MB; b++) {
                float sr = psum(ar[b])  + red[(0 * 8 + b) * 128 + jl];
                float sz = psum(az[b])  + red[(1 * 8 + b) * 128 + jl];
                float sn = psum(an_[b]) + red[(2 * 8 + b) * 128 + jl];
                float x0 = xb[b * TT * 2 + t * 2 + 0];
                float x1 = xb[b * TT * 2 + t * 2 + 1];
                float rg = sigm(sr + c0r + e0wr0 * x0 + e0wr1 * x1);
                float zg = sigm(sz + c0z + e0wz0 * x0 + e0wz1 * x1);
                float n  = tanhe(c0in + e0wn0 * x0 + e0wn1 * x1 + rg * (sn + c0hn));
                float hn = (1.f - zg) * n + zg * h0c[b * 256 + j];
                h0n[b * 256 + j] = hn;
                st_cluster(rem_base + (u32)(OFF_H0 + (s ^ 1) * 2048 + b * 256 + j) * 4u, hn);
            }
        }
        cluster_sync();

        // ---- layer 1 fused: gi = Wih1 @ h0n, gh = Whh1 @ h1c (full unroll) ----
        ull br_[MB], bz_[MB], bin_[MB], bhn_[MB];
        #pragma unroll
        for (int b = 0; b < MB; b++) { br_[b] = 0ull; bz_[b] = 0ull; bin_[b] = 0ull; bhn_[b] = 0ull; }
        #pragma unroll 32
        for (int k4 = k0; k4 < k0 + 32; k4++) {
            ulonglong2 ur = P1r[k4 * 256];
            ulonglong2 uz = P1z[k4 * 256];
            ulonglong2 un = P1n[k4 * 256];
            ulonglong2 vr = P2r[k4 * 256];
            ulonglong2 vz = P2z[k4 * 256];
            ulonglong2 vn = P2n[k4 * 256];
            #pragma unroll
            for (int b = 0; b < MB; b++) {
                ulonglong2 u = *(const ulonglong2*)&h0n[b * 256 + k4 * 4];
                fma2v(br_[b], ur, u); fma2v(bz_[b], uz, u); fma2v(bin_[b], un, u);
                ulonglong2 h = *(const ulonglong2*)&h1c[b * 256 + k4 * 4];
                fma2v(br_[b], vr, h); fma2v(bz_[b], vz, h); fma2v(bhn_[b], vn, h);
            }
        }
        if (ks) {
            #pragma unroll
            for (int b = 0; b < MB; b++) {
                red[(0 * 8 + b) * 128 + jl] = psum(br_[b]);
                red[(1 * 8 + b) * 128 + jl] = psum(bz_[b]);
                red[(2 * 8 + b) * 128 + jl] = psum(bin_[b]);
                red[(3 * 8 + b) * 128 + jl] = psum(bhn_[b]);
            }
        }
        __syncthreads();
        if (!ks) {
            #pragma unroll
            for (int b = 0; b < MB; b++) {
                float sr = psum(br_[b])  + red[(0 * 8 + b) * 128 + jl];
                float sz = psum(bz_[b])  + red[(1 * 8 + b) * 128 + jl];
                float si = psum(bin_[b]) + red[(2 * 8 + b) * 128 + jl];
                float sh = psum(bhn_[b]) + red[(3 * 8 + b) * 128 + jl];
                float rg = sigm(sr + c1r);
                float zg = sigm(sz + c1z);
                float n  = tanhe(si + c1in + rg * (sh + c1hn));
                float hn = (1.f - zg) * n + zg * h1c[b * 256 + j];
                h1n[b * 256 + j] = hn;
                st_cluster(rem_base + (u32)(OFF_H1 + (s ^ 1) * 2048 + b * 256 + j) * 4u, hn);
            }
        }
        cluster_sync();
        s ^= 1;
    }

    // z = tanh(h1_final @ fce_w.T + fce_b); each CTA does 4 of its 8 rows
    {
        const float* h1f = h1b + s * 2048;
        const int l  = tid & (LATD - 1);
        const int b0 = (int)rank * 4 + (tid >> 7) * 2;
        const float* wl = fce_w + (size_t)l * HH;
        for (int b = b0; b < b0 + 2; b++) {
            float acc = 0.f;
            #pragma unroll 8
            for (int k = 0; k < HH; k++) acc += wl[k] * h1f[b * 256 + k];
            float zz = tanhf(acc + fce_b[l]);
            g_z[(size_t)(base + b) * LATD + l] = zz;
            if (write_zout) z_out[(size_t)(base + b) * LATD + l] = zz;
        }
    }
    cluster_sync();
}

// ---------------------------------------------------------------------------
// Decoder
// ---------------------------------------------------------------------------
__global__ __launch_bounds__(NTH, 1) __cluster_dims__(2, 1, 1)
void dec_kernel(const float* __restrict__ Wih0,
                const float* __restrict__ bih0, const float* __restrict__ bhh0,
                const float* __restrict__ bih1, const float* __restrict__ bhh1,
                const float* __restrict__ fcd_w, const float* __restrict__ fcd_b,
                const float* __restrict__ fco_w, const float* __restrict__ fco_b,
                float* __restrict__ out)
{
    extern __shared__ __align__(16) float sm[];
    float* h0b = sm + OFF_H0;
    float* h1b = sm + OFF_H1;
    float* red = sm + OFF_RED;
    __shared__ float yb[MB][2];

    const int tid  = threadIdx.x;
    const int jl   = tid & 127;
    const int ks   = tid >> 7;
    const u32 rank = ctarank();
    const int j    = (int)rank * 128 + jl;
    const int base = (blockIdx.x >> 1) * MB;
    const int w    = tid >> 5;
    const int lane = tid & 31;

    // Init full h replica from fc_dec(z), raw row-major reshape:
    // dec_h[l][gb][u] = fcd_b[c'] + z[l*256+gb/2].fcd_w[c'], c' = (gb&1)*256+u
    {
        const int u = tid;
        #pragma unroll
        for (int b = 0; b < MB; b++) {
            int gb = base + b;
            int cr = ((gb & 1) << 8) + u;
            const float* wrow = fcd_w + (size_t)cr * LATD;
            const float* z0 = g_z + (size_t)(gb >> 1) * LATD;
            const float* z1 = g_z + (size_t)(256 + (gb >> 1)) * LATD;
            float a0 = fcd_b[cr], a1 = a0;
            #pragma unroll 8
            for (int k = 0; k < LATD; k++) {
                float wv = wrow[k];
                a0 += wv * z0[k];
                a1 += wv * z1[k];
            }
            h0b[b * 256 + u] = a0;
            h1b[b * 256 + u] = a1;
        }
    }
    if (tid < MB * 2) yb[tid >> 1][tid & 1] = 0.f;
    __syncthreads();

    const float d0wr0 = Wih0[j * 2 + 0],            d0wr1 = Wih0[j * 2 + 1];
    const float d0wz0 = Wih0[(HH + j) * 2 + 0],     d0wz1 = Wih0[(HH + j) * 2 + 1];
    const float d0wn0 = Wih0[(2 * HH + j) * 2 + 0], d0wn1 = Wih0[(2 * HH + j) * 2 + 1];
    const float c0r  = bih0[j] + bhh0[j];
    const float c0z  = bih0[HH + j] + bhh0[HH + j];
    const float c0in = bih0[2 * HH + j];
    const float c0hn = bhh0[2 * HH + j];
    const float c1r  = bih1[j] + bhh1[j];
    const float c1z  = bih1[HH + j] + bhh1[HH + j];
    const float c1in = bih1[2 * HH + j];
    const float c1hn = bhh1[2 * HH + j];

    const ulonglong2* P0r = g_Wp + (size_t) 9 * 16384 + j;
    const ulonglong2* P0z = g_Wp + (size_t)10 * 16384 + j;
    const ulonglong2* P0n = g_Wp + (size_t)11 * 16384 + j;
    const ulonglong2* P1r = g_Wp + (size_t)12 * 16384 + j;
    const ulonglong2* P1z = g_Wp + (size_t)13 * 16384 + j;
    const ulonglong2* P1n = g_Wp + (size_t)14 * 16384 + j;
    const ulonglong2* P2r = g_Wp + (size_t)15 * 16384 + j;
    const ulonglong2* P2z = g_Wp + (size_t)16 * 16384 + j;
    const ulonglong2* P2n = g_Wp + (size_t)17 * 16384 + j;

    const u32 loc_base = smem_u32(sm);
    const u32 rem_base = mapa_rank(loc_base, rank ^ 1);
    const int k0 = ks * 32;
    cluster_sync();

    int s = 0;
    for (int t = 0; t < TT; t++) {
        const float* h0c = h0b + s * 2048;
        float*       h0n = h0b + (s ^ 1) * 2048;
        const float* h1c = h1b + s * 2048;
        float*       h1n = h1b + (s ^ 1) * 2048;

        // ---- layer 0 matvec (full unroll) ----
        ull ar[MB], az[MB], an_[MB];
        #pragma unroll
        for (int b = 0; b < MB; b++) { ar[b] = 0ull; az[b] = 0ull; an_[b] = 0ull; }
        #pragma unroll 32
        for (int k4 = k0; k4 < k0 + 32; k4++) {
            ulonglong2 wr = P0r[k4 * 256];
            ulonglong2 wz = P0z[k4 * 256];
            ulonglong2 wn = P0n[k4 * 256];
            #pragma unroll
            for (int b = 0; b < MB; b++) {
                ulonglong2 h = *(const ulonglong2*)&h0c[b * 256 + k4 * 4];
                fma2v(ar[b], wr, h); fma2v(az[b], wz, h); fma2v(an_[b], wn, h);
            }
        }
        if (ks) {
            #pragma unroll
            for (int b = 0; b < MB; b++) {
                red[(0 * 8 + b) * 128 + jl] = psum(ar[b]);
                red[(1 * 8 + b) * 128 + jl] = psum(az[b]);
                red[(2 * 8 + b) * 128 + jl] = psum(an_[b]);
            }
        }
        __syncthreads();
        if (!ks) {
            #pragma unroll
            for (int b = 0; b < MB; b++) {
                float sr = psum(ar[b])  + red[(0 * 8 + b) * 128 + jl];
                float sz = psum(az[b])  + red[(1 * 8 + b) * 128 + jl];
                float sn = psum(an_[b]) + red[(2 * 8 + b) * 128 + jl];
                float x0 = yb[b][0], x1 = yb[b][1];
                float rg = sigm(sr + c0r + d0wr0 * x0 + d0wr1 * x1);
                float zg = sigm(sz + c0z + d0wz0 * x0 + d0wz1 * x1);
                float n  = tanhe(c0in + d0wn0 * x0 + d0wn1 * x1 + rg * (sn + c0hn));
                float hn = (1.f - zg) * n + zg * h0c[b * 256 + j];
                h0n[b * 256 + j] = hn;
                st_cluster(rem_base + (u32)(OFF_H0 + (s ^ 1) * 2048 + b * 256 + j) * 4u, hn);
            }
        }
        cluster_sync();

        // ---- layer 1 fused (full unroll) ----
        ull br_[MB], bz_[MB], bin_[MB], bhn_[MB];
        #pragma unroll
        for (int b = 0; b < MB; b++) { br_[b] = 0ull; bz_[b] = 0ull; bin_[b] = 0ull; bhn_[b] = 0ull; }
        #pragma unroll 32
        for (int k4 = k0; k4 < k0 + 32; k4++) {
            ulonglong2 ur = P1r[k4 * 256];
            ulonglong2 uz = P1z[k4 * 256];
            ulonglong2 un = P1n[k4 * 256];
            ulonglong2 vr = P2r[k4 * 256];
            ulonglong2 vz = P2z[k4 * 256];
            ulonglong2 vn = P2n[k4 * 256];
            #pragma unroll
            for (int b = 0; b < MB; b++) {
                ulonglong2 u = *(const ulonglong2*)&h0n[b * 256 + k4 * 4];
                fma2v(br_[b], ur, u); fma2v(bz_[b], uz, u); fma2v(bin_[b], un, u);
                ulonglong2 h = *(const ulonglong2*)&h1c[b * 256 + k4 * 4];
                fma2v(br_[b], vr, h); fma2v(bz_[b], vz, h); fma2v(bhn_[b], vn, h);
            }
        }
        if (ks) {
            #pragma unroll
            for (int b = 0; b < MB; b++) {
                red[(0 * 8 + b) * 128 + jl] = psum(br_[b]);
                red[(1 * 8 + b) * 128 + jl] = psum(bz_[b]);
                red[(2 * 8 + b) * 128 + jl] = psum(bin_[b]);
                red[(3 * 8 + b) * 128 + jl] = psum(bhn_[b]);
            }
        }
        __syncthreads();
        if (!ks) {
            #pragma unroll
            for (int b = 0; b < MB; b++) {
                float sr = psum(br_[b])  + red[(0 * 8 + b) * 128 + jl];
                float sz = psum(bz_[b])  + red[(1 * 8 + b) * 128 + jl];
                float si = psum(bin_[b]) + red[(2 * 8 + b) * 128 + jl];
                float sh = psum(bhn_[b]) + red[(3 * 8 + b) * 128 + jl];
                float rg = sigm(sr + c1r);
                float zg = sigm(sz + c1z);
                float n  = tanhe(si + c1in + rg * (sh + c1hn));
                float hn = (1.f - zg) * n + zg * h1c[b * 256 + j];
                h1n[b * 256 + j] = hn;
                st_cluster(rem_base + (u32)(OFF_H1 + (s ^ 1) * 2048 + b * 256 + j) * 4u, hn);
            }
        }
        cluster_sync();

        // ---- output head: warps 0..7 -> rows 0..7 (full h1n valid now) ----
        {
            const int b = w;
            float a0 = 0.f, a1 = 0.f;
            const float* w0 = fco_w;
            const float* w1 = fco_w + HH;
            #pragma unroll
            for (int k = lane; k < HH; k += 32) {
                float hv = h1n[b * 256 + k];
                a0 += w0[k] * hv;
                a1 += w1[k] * hv;
            }
            #pragma unroll
            for (int o = 16; o > 0; o >>= 1) {
                a0 += __shfl_xor_sync(0xffffffffu, a0, o);
                a1 += __shfl_xor_sync(0xffffffffu, a1, o);
            }
            if (lane == 0) {
                float y0 = a0 + fco_b[0];
                float y1 = a1 + fco_b[1];
                yb[b][0] = y0;
                yb[b][1] = y1;
                if (rank == 0) {
                    int gb = base + b;
                    out[((size_t)gb * TT + t) * 2 + 0] = y0;
                    out[((size_t)gb * TT + t) * 2 + 1] = y1;
                }
            }
        }
        __syncthreads();
        s ^= 1;
    }
    cluster_sync();
}

// ---------------------------------------------------------------------------
extern "C" void kernel_launch(void* const* d_in, const int* in_sizes, int n_in,
                              void* d_out, int out_size) {
    const float* x        = (const float*)d_in[0];
    const float* ln_w     = (const float*)d_in[1];
    const float* ln_b     = (const float*)d_in[2];
    const float* enc_Wih0 = (const float*)d_in[3];
    const float* enc_Whh0 = (const float*)d_in[4];
    const float* enc_bih0 = (const float*)d_in[5];
    const float* enc_bhh0 = (const float*)d_in[6];
    const float* enc_Wih1 = (const float*)d_in[7];
    const float* enc_Whh1 = (const float*)d_in[8];
    const float* enc_bih1 = (const float*)d_in[9];
    const float* enc_bhh1 = (const float*)d_in[10];
    const float* dec_Wih0 = (const float*)d_in[11];
    const float* dec_Whh0 = (const float*)d_in[12];
    const float* dec_bih0 = (const float*)d_in[13];
    const float* dec_bhh0 = (const float*)d_in[14];
    const float* dec_Wih1 = (const float*)d_in[15];
    const float* dec_Whh1 = (const float*)d_in[16];
    const float* dec_bih1 = (const float*)d_in[17];
    const float* dec_bhh1 = (const float*)d_in[18];
    const float* fc_enc_w = (const float*)d_in[19];
    const float* fc_enc_b = (const float*)d_in[20];
    const float* fc_dec_w = (const float*)d_in[21];
    const float* fc_dec_b = (const float*)d_in[22];
    const float* fc_out_w = (const float*)d_in[23];
    const float* fc_out_b = (const float*)d_in[24];

    float* out = (float*)d_out;
    const int recon_elems = BB * TT * 2;             // 184320
    const int z_elems     = BB * LATD;               // 65536
    int write_z = (out_size >= recon_elems + z_elems) ? 1 : 0;
    float* z_out = out + recon_elems;

    static int attr_done = 0;
    if (!attr_done) {
        cudaFuncSetAttribute(enc_kernel, cudaFuncAttributeMaxDynamicSharedMemorySize,
                             ENC_SMEM_FLOATS * 4);
        cudaFuncSetAttribute(dec_kernel, cudaFuncAttributeMaxDynamicSharedMemorySize,
                             DEC_SMEM_FLOATS * 4);
        attr_done = 1;
    }

    pack_kernel<<<6 * 192, 256>>>(enc_Whh0, enc_Wih1, enc_Whh1,
                                  dec_Whh0, dec_Wih1, dec_Whh1);

    enc_kernel<<<NB2, NTH, ENC_SMEM_FLOATS * 4>>>(
        x, ln_w, ln_b, enc_Wih0, enc_bih0, enc_bhh0,
        enc_bih1, enc_bhh1, fc_enc_w, fc_enc_b, z_out, write_z);

    dec_kernel<<<NB2, NTH, DEC_SMEM_FLOATS * 4>>>(
        dec_Wih0, dec_bih0, dec_bhh0, dec_bih1, dec_bhh1,
        fc_dec_w, fc_dec_b, fc_out_w, fc_out_b, out);
}